// round 1
// baseline (speedup 1.0000x reference)
#include <cuda_runtime.h>
#include <math.h>

#define NBATCH 16
#define LSEQ   4096
#define DIN    64
#define HCH    256
#define NST    32
#define NLAY   4
#define DOUT   10

// ---------------------------------------------------------------------------
// Scratch (device globals; no allocation allowed)
// ---------------------------------------------------------------------------
__device__ float g_h[NBATCH * HCH * LSEQ];            // layer activations (B,H,L)
__device__ float g_y[NBATCH * HCH * LSEQ];            // post-gelu SSM output (B,H,L)
__device__ float g_par[NLAY][4][HCH * NST];           // w_re, w_im, 2*Ct_re, -2*Ct_im

// ---------------------------------------------------------------------------
// Per-layer SSM parameter precompute:
//   A  = -exp(log_A_real) + i*A_imag ; dt = exp(log_dt)
//   w  = exp(dt*A)
//   C' = (C_re + i C_im) * expm1(dt*A) / A
// Stored so the scan does: contrib = ca*s_re + cb*s_im  (== 2*Re(C' * s))
// ---------------------------------------------------------------------------
__global__ void params_kernel(const float* __restrict__ log_dt,
                              const float* __restrict__ log_A_real,
                              const float* __restrict__ A_imag,
                              const float* __restrict__ C_re,
                              const float* __restrict__ C_im) {
    int idx = blockIdx.x * blockDim.x + threadIdx.x;
    if (idx >= NLAY * HCH * NST) return;
    int layer = idx / (HCH * NST);
    int hn    = idx - layer * (HCH * NST);
    int h     = hn / NST;

    float dt  = expf(log_dt[layer * HCH + h]);
    float Are = -expf(log_A_real[idx]);
    float Aim = A_imag[idx];
    float dre = Are * dt;
    float dimg = Aim * dt;

    float sy, cy;
    sincosf(dimg, &sy, &cy);
    float em1 = expm1f(dre);          // exp(dre) - 1, stable for small dre
    float ex  = em1 + 1.0f;           // exp(dre)
    float wre = ex * cy;
    float wim = ex * sy;
    // expm1(dt*A) = (exp(x)cos y - 1) + i exp(x) sin y, computed stably:
    float emr = fmaf(em1, cy, cy - 1.0f);
    float emi = ex * sy;

    float inv = 1.0f / fmaf(Are, Are, Aim * Aim);
    float tre = fmaf(emr, Are, emi * Aim) * inv;     // (em / A)_re
    float tim = fmaf(emi, Are, -emr * Aim) * inv;    // (em / A)_im

    float cre = C_re[idx], cim = C_im[idx];
    float ctre = fmaf(cre, tre, -cim * tim);
    float ctim = fmaf(cre, tim, cim * tre);

    g_par[layer][0][hn] = wre;
    g_par[layer][1][hn] = wim;
    g_par[layer][2][hn] = 2.0f * ctre;
    g_par[layer][3][hn] = -2.0f * ctim;
}

// ---------------------------------------------------------------------------
// Encoder: h[b,h,l] = sum_i x[b,l,i]*enc_w[h,i] + enc_b[h]   (writes (B,H,L))
// Block = (b, 64-l tile), 256 threads, 8x8 register microtiles.
// ---------------------------------------------------------------------------
__global__ void __launch_bounds__(256) encoder_kernel(
    const float* __restrict__ x,
    const float* __restrict__ enc_w,
    const float* __restrict__ enc_b) {
    extern __shared__ float sm[];
    float* Wsh = sm;               // [64][256]   (i, h)
    float* Xsh = sm + 64 * HCH;    // [64][68]    (i, l) padded

    int b    = blockIdx.y;
    int pos0 = blockIdx.x * 64;
    int tid  = threadIdx.x;

    // enc_w row h=tid -> transposed into Wsh[i][h]
    {
        const float4* wrow = (const float4*)(enc_w + (size_t)tid * DIN);
#pragma unroll
        for (int q = 0; q < 16; q++) {
            float4 v = wrow[q];
            Wsh[(q * 4 + 0) * HCH + tid] = v.x;
            Wsh[(q * 4 + 1) * HCH + tid] = v.y;
            Wsh[(q * 4 + 2) * HCH + tid] = v.z;
            Wsh[(q * 4 + 3) * HCH + tid] = v.w;
        }
    }
    // x tile (64 l x 64 i) -> transposed into Xsh[i][l]
    {
#pragma unroll
        for (int k = 0; k < 4; k++) {
            int e  = tid + k * 256;     // float4 id
            int l  = e >> 4;
            int i4 = e & 15;
            const float4* xr =
                (const float4*)(x + ((size_t)(b * LSEQ) + pos0 + l) * DIN);
            float4 v = xr[i4];
            Xsh[(i4 * 4 + 0) * 68 + l] = v.x;
            Xsh[(i4 * 4 + 1) * 68 + l] = v.y;
            Xsh[(i4 * 4 + 2) * 68 + l] = v.z;
            Xsh[(i4 * 4 + 3) * 68 + l] = v.w;
        }
    }
    __syncthreads();

    int th = tid >> 3;   // 0..31 -> h tile
    int tl = tid & 7;    // 0..7  -> l tile
    float acc[8][8];
#pragma unroll
    for (int r = 0; r < 8; r++)
#pragma unroll
        for (int c = 0; c < 8; c++) acc[r][c] = 0.0f;

    for (int i = 0; i < DIN; i++) {
        float4 a0 = *(const float4*)&Wsh[i * HCH + th * 8];
        float4 a1 = *(const float4*)&Wsh[i * HCH + th * 8 + 4];
        float4 b0 = *(const float4*)&Xsh[i * 68 + tl * 8];
        float4 b1 = *(const float4*)&Xsh[i * 68 + tl * 8 + 4];
        float av[8] = {a0.x, a0.y, a0.z, a0.w, a1.x, a1.y, a1.z, a1.w};
        float bv[8] = {b0.x, b0.y, b0.z, b0.w, b1.x, b1.y, b1.z, b1.w};
#pragma unroll
        for (int r = 0; r < 8; r++)
#pragma unroll
            for (int c = 0; c < 8; c++)
                acc[r][c] = fmaf(av[r], bv[c], acc[r][c]);
    }

#pragma unroll
    for (int r = 0; r < 8; r++) {
        int h = th * 8 + r;
        float bias = __ldg(&enc_b[h]);
        float* dst = g_h + ((size_t)(b * HCH + h)) * LSEQ + pos0 + tl * 8;
        float4 o0 = make_float4(acc[r][0] + bias, acc[r][1] + bias,
                                acc[r][2] + bias, acc[r][3] + bias);
        float4 o1 = make_float4(acc[r][4] + bias, acc[r][5] + bias,
                                acc[r][6] + bias, acc[r][7] + bias);
        ((float4*)dst)[0] = o0;
        ((float4*)dst)[1] = o1;
    }
}

// ---------------------------------------------------------------------------
// SSM scan + D-skip + GELU. One warp per channel (b,h); lane = state n.
//   s = w*s + z[l]   (complex, diagonal)
//   y[l] = sum_n (ca*s_re + cb*s_im) + D*z[l];  out = gelu(y)
// Reduction over n done via a 32x33 shared transpose every 32 steps.
// ---------------------------------------------------------------------------
__global__ void __launch_bounds__(256) scan_kernel(const float* __restrict__ Dvec,
                                                   int layer) {
    __shared__ float sh[8][32][33];
    int wid  = threadIdx.x >> 5;
    int lane = threadIdx.x & 31;
    int c    = blockIdx.x * 8 + wid;        // channel 0..4095
    int h    = c & (HCH - 1);

    const float* par = &g_par[layer][0][0];
    float wre = par[0 * (HCH * NST) + h * NST + lane];
    float wim = par[1 * (HCH * NST) + h * NST + lane];
    float ca  = par[2 * (HCH * NST) + h * NST + lane];
    float cb  = par[3 * (HCH * NST) + h * NST + lane];
    float Dh  = __ldg(&Dvec[layer * HCH + h]);

    const float* zin = g_h + (size_t)c * LSEQ;
    float*       yout = g_y + (size_t)c * LSEQ;
    float (*S)[33] = sh[wid];

    float sre = 0.0f, sim = 0.0f;
    for (int l0 = 0; l0 < LSEQ; l0 += 32) {
        float zv = zin[l0 + lane];
#pragma unroll
        for (int t = 0; t < 32; t++) {
            float z  = __shfl_sync(0xffffffffu, zv, t);
            float nr = fmaf(wre, sre, z);
            nr       = fmaf(-wim, sim, nr);
            float ni = fmaf(wim, sre, wre * sim);
            sre = nr;
            sim = ni;
            S[lane][t] = fmaf(ca, sre, cb * sim);
        }
        __syncwarp();
        float acc = 0.0f;
#pragma unroll
        for (int n = 0; n < 32; n++) acc += S[n][lane];
        float yv = fmaf(Dh, zv, acc);
        // gelu (tanh approximation, matching jax.nn.gelu default)
        float u  = 0.7978845608028654f * fmaf(0.044715f, yv * yv * yv, yv);
        float gv = 0.5f * yv * (1.0f + tanhf(u));
        yout[l0 + lane] = gv;
        __syncwarp();
    }
}

// ---------------------------------------------------------------------------
// Fused: g = out_w @ y + out_b (512 outputs); GLU; + residual; channel-LN.
// Block = (b, 64-position tile), 512 threads. 8x8 register microtiles.
// Dynamic smem: Rsh[256][64] | union( Wsh[32][512]+Ysh[32][68] , Gsh[512][68] )
// ---------------------------------------------------------------------------
__global__ void __launch_bounds__(512) glu_ln_kernel(
    const float* __restrict__ out_w, const float* __restrict__ out_b,
    const float* __restrict__ ln_w,  const float* __restrict__ ln_b,
    int layer) {
    extern __shared__ float sm[];
    float* Rsh = sm;                        // 256*64
    float* Wsh = sm + 16384;                // 32*512
    float* Ysh = sm + 16384 + 16384;        // 32*68
    float* Gsh = sm + 16384;                // 512*68 (overlaps Wsh/Ysh, phase B)
    __shared__ float redS[8][64];
    __shared__ float redQ[8][64];

    int b    = blockIdx.y;
    int pos0 = blockIdx.x * 64;
    int tid  = threadIdx.x;
    const float* wlay = out_w + (size_t)layer * 512 * HCH;

    // residual tile (coalesced rows of l)
#pragma unroll
    for (int k = 0; k < 8; k++) {
        int e  = tid + k * 512;     // float4 id 0..4095
        int h  = e >> 4;
        int p4 = e & 15;
        float4 v = *(const float4*)(g_h + ((size_t)(b * HCH + h)) * LSEQ +
                                    pos0 + p4 * 4);
        *(float4*)&Rsh[h * 64 + p4 * 4] = v;
    }

    int tj = tid >> 3;   // 0..63 -> j tile (8 consecutive j)
    int tp = tid & 7;    // 0..7  -> pos tile (8 consecutive pos)
    float acc[8][8];
#pragma unroll
    for (int r = 0; r < 8; r++)
#pragma unroll
        for (int c = 0; c < 8; c++) acc[r][c] = 0.0f;

    for (int k0 = 0; k0 < HCH; k0 += 32) {
        __syncthreads();
        // Wsh[kk][j] <- out_w[j][k0+kk]   (thread t owns row j=t)
        {
            const float4* wr = (const float4*)(wlay + (size_t)tid * HCH + k0);
#pragma unroll
            for (int q = 0; q < 8; q++) {
                float4 v = wr[q];
                Wsh[(q * 4 + 0) * 512 + tid] = v.x;
                Wsh[(q * 4 + 1) * 512 + tid] = v.y;
                Wsh[(q * 4 + 2) * 512 + tid] = v.z;
                Wsh[(q * 4 + 3) * 512 + tid] = v.w;
            }
        }
        // Ysh[kk][pos]
        {
            int kk = tid >> 4;
            int p4 = tid & 15;
            float4 v = *(const float4*)(g_y +
                                        ((size_t)(b * HCH + k0 + kk)) * LSEQ +
                                        pos0 + p4 * 4);
            *(float4*)&Ysh[kk * 68 + p4 * 4] = v;
        }
        __syncthreads();
#pragma unroll
        for (int kk = 0; kk < 32; kk++) {
            float4 a0 = *(const float4*)&Wsh[kk * 512 + tj * 8];
            float4 a1 = *(const float4*)&Wsh[kk * 512 + tj * 8 + 4];
            float4 b0 = *(const float4*)&Ysh[kk * 68 + tp * 8];
            float4 b1 = *(const float4*)&Ysh[kk * 68 + tp * 8 + 4];
            float av[8] = {a0.x, a0.y, a0.z, a0.w, a1.x, a1.y, a1.z, a1.w};
            float bv[8] = {b0.x, b0.y, b0.z, b0.w, b1.x, b1.y, b1.z, b1.w};
#pragma unroll
            for (int r = 0; r < 8; r++)
#pragma unroll
                for (int c = 0; c < 8; c++)
                    acc[r][c] = fmaf(av[r], bv[c], acc[r][c]);
        }
    }
    __syncthreads();

    // bias + stage g into Gsh[j][pos]
#pragma unroll
    for (int r = 0; r < 8; r++) {
        int j = tj * 8 + r;
        float bias = __ldg(&out_b[layer * 512 + j]);
        float4 o0 = make_float4(acc[r][0] + bias, acc[r][1] + bias,
                                acc[r][2] + bias, acc[r][3] + bias);
        float4 o1 = make_float4(acc[r][4] + bias, acc[r][5] + bias,
                                acc[r][6] + bias, acc[r][7] + bias);
        *(float4*)&Gsh[j * 68 + tp * 8]     = o0;
        *(float4*)&Gsh[j * 68 + tp * 8 + 4] = o1;
    }
    __syncthreads();

    // GLU + residual + channel LayerNorm
    int grp = tid >> 6;   // 0..7  -> 32 channels each
    int pos = tid & 63;
    float uv[32];
    float sum = 0.0f, sq = 0.0f;
#pragma unroll
    for (int r = 0; r < 32; r++) {
        int h = grp * 32 + r;
        float g1 = Gsh[h * 68 + pos];
        float g2 = Gsh[(h + 256) * 68 + pos];
        float sg = 1.0f / (1.0f + expf(-g2));
        float u  = fmaf(g1, sg, Rsh[h * 64 + pos]);
        uv[r] = u;
        sum += u;
        sq = fmaf(u, u, sq);
    }
    redS[grp][pos] = sum;
    redQ[grp][pos] = sq;
    __syncthreads();
    float tot = 0.0f, totq = 0.0f;
#pragma unroll
    for (int g8 = 0; g8 < 8; g8++) {
        tot  += redS[g8][pos];
        totq += redQ[g8][pos];
    }
    float mean = tot * (1.0f / 256.0f);
    float var  = fmaf(-mean, mean, totq * (1.0f / 256.0f));
    float rs   = rsqrtf(var + 1e-5f);
#pragma unroll
    for (int r = 0; r < 32; r++) {
        int h = grp * 32 + r;
        float w  = __ldg(&ln_w[layer * HCH + h]);
        float bb = __ldg(&ln_b[layer * HCH + h]);
        float val = fmaf((uv[r] - mean) * rs, w, bb);
        g_h[((size_t)(b * HCH + h)) * LSEQ + pos0 + pos] = val;
    }
}

// ---------------------------------------------------------------------------
// Decoder: out[b,l,o] = sum_h h[b,h,l]*dec_w[o,h] + dec_b[o]
// ---------------------------------------------------------------------------
__global__ void __launch_bounds__(256) decoder_kernel(
    const float* __restrict__ dec_w, const float* __restrict__ dec_b,
    float* __restrict__ out) {
    __shared__ float wsh[DOUT * HCH];
    __shared__ float bsh[DOUT];
    int b    = blockIdx.y;
    int pos0 = blockIdx.x * 256;
    int tid  = threadIdx.x;
    for (int e = tid; e < DOUT * HCH; e += 256) wsh[e] = dec_w[e];
    if (tid < DOUT) bsh[tid] = dec_b[tid];
    __syncthreads();

    float acc[DOUT];
#pragma unroll
    for (int o = 0; o < DOUT; o++) acc[o] = bsh[o];

    const float* hp = g_h + (size_t)b * HCH * LSEQ + pos0 + tid;
    for (int h = 0; h < HCH; h++) {
        float xv = hp[(size_t)h * LSEQ];
#pragma unroll
        for (int o = 0; o < DOUT; o++)
            acc[o] = fmaf(xv, wsh[o * HCH + h], acc[o]);
    }
    float* op = out + ((size_t)(b * LSEQ) + pos0 + tid) * DOUT;
#pragma unroll
    for (int o = 0; o < DOUT; o++) op[o] = acc[o];
}

// ---------------------------------------------------------------------------
extern "C" void kernel_launch(void* const* d_in, const int* in_sizes, int n_in,
                              void* d_out, int out_size) {
    const float* x          = (const float*)d_in[0];
    const float* enc_w      = (const float*)d_in[1];
    const float* enc_b      = (const float*)d_in[2];
    const float* log_dt     = (const float*)d_in[3];
    const float* log_A_real = (const float*)d_in[4];
    const float* A_imag     = (const float*)d_in[5];
    const float* C_re       = (const float*)d_in[6];
    const float* C_im       = (const float*)d_in[7];
    const float* Dv         = (const float*)d_in[8];
    const float* out_w      = (const float*)d_in[9];
    const float* out_b      = (const float*)d_in[10];
    const float* ln_w       = (const float*)d_in[11];
    const float* ln_b       = (const float*)d_in[12];
    const float* dec_w      = (const float*)d_in[13];
    const float* dec_b      = (const float*)d_in[14];
    float* out = (float*)d_out;

    size_t enc_smem = (size_t)(64 * HCH + 64 * 68) * sizeof(float);      // ~83 KB
    size_t glu_smem = (size_t)(16384 + 512 * 68) * sizeof(float);        // 204800 B
    cudaFuncSetAttribute(encoder_kernel,
                         cudaFuncAttributeMaxDynamicSharedMemorySize,
                         (int)enc_smem);
    cudaFuncSetAttribute(glu_ln_kernel,
                         cudaFuncAttributeMaxDynamicSharedMemorySize,
                         (int)glu_smem);

    params_kernel<<<(NLAY * HCH * NST + 255) / 256, 256>>>(
        log_dt, log_A_real, A_imag, C_re, C_im);
    encoder_kernel<<<dim3(LSEQ / 64, NBATCH), 256, enc_smem>>>(x, enc_w, enc_b);
    for (int layer = 0; layer < NLAY; layer++) {
        scan_kernel<<<512, 256>>>(Dv, layer);
        glu_ln_kernel<<<dim3(LSEQ / 64, NBATCH), 512, glu_smem>>>(
            out_w, out_b, ln_w, ln_b, layer);
    }
    decoder_kernel<<<dim3(LSEQ / 256, NBATCH), 256>>>(dec_w, dec_b, out);
}

// round 2
// speedup vs baseline: 1.0167x; 1.0167x over previous
#include <cuda_runtime.h>
#include <math.h>

#define NBATCH 16
#define LSEQ   4096
#define DIN    64
#define HCH    256
#define NST    32
#define NLAY   4
#define DOUT   10

// ---------------------------------------------------------------------------
// Packed fp32x2 helpers (sm_103a FFMA2 — ptxas never auto-fuses; PTX only)
// ---------------------------------------------------------------------------
__device__ __forceinline__ unsigned long long pack2(float x, float y) {
    unsigned long long r;
    asm("mov.b64 %0, {%1, %2};" : "=l"(r) : "f"(x), "f"(y));
    return r;
}
__device__ __forceinline__ void fma2(unsigned long long& d,
                                     unsigned long long a,
                                     unsigned long long b) {
    asm("fma.rn.f32x2 %0, %1, %2, %0;" : "+l"(d) : "l"(a), "l"(b));
}
__device__ __forceinline__ float2 unpack2(unsigned long long v) {
    float2 r;
    asm("mov.b64 {%0, %1}, %2;" : "=f"(r.x), "=f"(r.y) : "l"(v));
    return r;
}

// ---------------------------------------------------------------------------
// Scratch (device globals; no allocation allowed)
// ---------------------------------------------------------------------------
__device__ float g_h[NBATCH * HCH * LSEQ];            // layer activations (B,H,L)
__device__ float g_y[NBATCH * HCH * LSEQ];            // post-gelu SSM output (B,H,L)
__device__ float g_par[NLAY][4][HCH * NST];           // w_re, w_im, 2*Ct_re, -2*Ct_im

// ---------------------------------------------------------------------------
// Per-layer SSM parameter precompute.
// ---------------------------------------------------------------------------
__global__ void params_kernel(const float* __restrict__ log_dt,
                              const float* __restrict__ log_A_real,
                              const float* __restrict__ A_imag,
                              const float* __restrict__ C_re,
                              const float* __restrict__ C_im) {
    int idx = blockIdx.x * blockDim.x + threadIdx.x;
    if (idx >= NLAY * HCH * NST) return;
    int layer = idx / (HCH * NST);
    int hn    = idx - layer * (HCH * NST);
    int h     = hn / NST;

    float dt  = expf(log_dt[layer * HCH + h]);
    float Are = -expf(log_A_real[idx]);
    float Aim = A_imag[idx];
    float dre = Are * dt;
    float dimg = Aim * dt;

    float sy, cy;
    sincosf(dimg, &sy, &cy);
    float em1 = expm1f(dre);
    float ex  = em1 + 1.0f;
    float wre = ex * cy;
    float wim = ex * sy;
    float emr = fmaf(em1, cy, cy - 1.0f);
    float emi = ex * sy;

    float inv = 1.0f / fmaf(Are, Are, Aim * Aim);
    float tre = fmaf(emr, Are, emi * Aim) * inv;
    float tim = fmaf(emi, Are, -emr * Aim) * inv;

    float cre = C_re[idx], cim = C_im[idx];
    float ctre = fmaf(cre, tre, -cim * tim);
    float ctim = fmaf(cre, tim, cim * tre);

    g_par[layer][0][hn] = wre;
    g_par[layer][1][hn] = wim;
    g_par[layer][2][hn] = 2.0f * ctre;
    g_par[layer][3][hn] = -2.0f * ctim;
}

// ---------------------------------------------------------------------------
// Encoder: h[b,h,l] = sum_i x[b,l,i]*enc_w[h,i] + enc_b[h]   (writes (B,H,L))
// ---------------------------------------------------------------------------
__global__ void __launch_bounds__(256) encoder_kernel(
    const float* __restrict__ x,
    const float* __restrict__ enc_w,
    const float* __restrict__ enc_b) {
    extern __shared__ float sm[];
    float* Wsh = sm;               // [64][256]
    float* Xsh = sm + 64 * HCH;    // [64][68]

    int b    = blockIdx.y;
    int pos0 = blockIdx.x * 64;
    int tid  = threadIdx.x;

    {
        const float4* wrow = (const float4*)(enc_w + (size_t)tid * DIN);
#pragma unroll
        for (int q = 0; q < 16; q++) {
            float4 v = wrow[q];
            Wsh[(q * 4 + 0) * HCH + tid] = v.x;
            Wsh[(q * 4 + 1) * HCH + tid] = v.y;
            Wsh[(q * 4 + 2) * HCH + tid] = v.z;
            Wsh[(q * 4 + 3) * HCH + tid] = v.w;
        }
    }
    {
#pragma unroll
        for (int k = 0; k < 4; k++) {
            int e  = tid + k * 256;
            int l  = e >> 4;
            int i4 = e & 15;
            const float4* xr =
                (const float4*)(x + ((size_t)(b * LSEQ) + pos0 + l) * DIN);
            float4 v = xr[i4];
            Xsh[(i4 * 4 + 0) * 68 + l] = v.x;
            Xsh[(i4 * 4 + 1) * 68 + l] = v.y;
            Xsh[(i4 * 4 + 2) * 68 + l] = v.z;
            Xsh[(i4 * 4 + 3) * 68 + l] = v.w;
        }
    }
    __syncthreads();

    int th = tid >> 3;
    int tl = tid & 7;
    unsigned long long acc2[8][4];
#pragma unroll
    for (int r = 0; r < 8; r++)
#pragma unroll
        for (int c = 0; c < 4; c++) acc2[r][c] = 0ULL;

    for (int i = 0; i < DIN; i++) {
        float4 a0 = *(const float4*)&Wsh[i * HCH + th * 8];
        float4 a1 = *(const float4*)&Wsh[i * HCH + th * 8 + 4];
        ulonglong2 b0 = *(const ulonglong2*)&Xsh[i * 68 + tl * 8];
        ulonglong2 b1 = *(const ulonglong2*)&Xsh[i * 68 + tl * 8 + 4];
        unsigned long long bv[4] = {b0.x, b0.y, b1.x, b1.y};
        float av[8] = {a0.x, a0.y, a0.z, a0.w, a1.x, a1.y, a1.z, a1.w};
#pragma unroll
        for (int r = 0; r < 8; r++) {
            unsigned long long ar = pack2(av[r], av[r]);
#pragma unroll
            for (int c = 0; c < 4; c++) fma2(acc2[r][c], ar, bv[c]);
        }
    }

#pragma unroll
    for (int r = 0; r < 8; r++) {
        int h = th * 8 + r;
        float bias = __ldg(&enc_b[h]);
        float* dst = g_h + ((size_t)(b * HCH + h)) * LSEQ + pos0 + tl * 8;
        float2 p0 = unpack2(acc2[r][0]);
        float2 p1 = unpack2(acc2[r][1]);
        float2 p2 = unpack2(acc2[r][2]);
        float2 p3 = unpack2(acc2[r][3]);
        float4 o0 = make_float4(p0.x + bias, p0.y + bias, p1.x + bias, p1.y + bias);
        float4 o1 = make_float4(p2.x + bias, p2.y + bias, p3.x + bias, p3.y + bias);
        ((float4*)dst)[0] = o0;
        ((float4*)dst)[1] = o1;
    }
}

// ---------------------------------------------------------------------------
// SSM scan + D-skip + GELU. One warp per channel (b,h); lane = state n.
// ---------------------------------------------------------------------------
__global__ void __launch_bounds__(256) scan_kernel(const float* __restrict__ Dvec,
                                                   int layer) {
    __shared__ float sh[8][32][33];
    int wid  = threadIdx.x >> 5;
    int lane = threadIdx.x & 31;
    int c    = blockIdx.x * 8 + wid;
    int h    = c & (HCH - 1);

    const float* par = &g_par[layer][0][0];
    float wre = par[0 * (HCH * NST) + h * NST + lane];
    float wim = par[1 * (HCH * NST) + h * NST + lane];
    float ca  = par[2 * (HCH * NST) + h * NST + lane];
    float cb  = par[3 * (HCH * NST) + h * NST + lane];
    float Dh  = __ldg(&Dvec[layer * HCH + h]);

    const float* zin  = g_h + (size_t)c * LSEQ;
    float*       yout = g_y + (size_t)c * LSEQ;
    float (*S)[33] = sh[wid];

    float sre = 0.0f, sim = 0.0f;
    for (int l0 = 0; l0 < LSEQ; l0 += 32) {
        float zv = zin[l0 + lane];
#pragma unroll
        for (int t = 0; t < 32; t++) {
            float z  = __shfl_sync(0xffffffffu, zv, t);
            float nr = fmaf(wre, sre, z);
            nr       = fmaf(-wim, sim, nr);
            float ni = fmaf(wim, sre, wre * sim);
            sre = nr;
            sim = ni;
            S[lane][t] = fmaf(ca, sre, cb * sim);
        }
        __syncwarp();
        float acc = 0.0f;
#pragma unroll
        for (int n = 0; n < 32; n++) acc += S[n][lane];
        float yv = fmaf(Dh, zv, acc);
        float u  = 0.7978845608028654f * fmaf(0.044715f, yv * yv * yv, yv);
        float gv = 0.5f * yv * (1.0f + tanhf(u));
        yout[l0 + lane] = gv;
        __syncwarp();
    }
}

// ---------------------------------------------------------------------------
// Fused: g = out_w @ y + out_b (512 outputs); GLU; + residual; channel-LN.
// Mainloop uses packed fma.rn.f32x2 (FFMA2) — 32 packed FMAs per kk vs 64.
// ---------------------------------------------------------------------------
__global__ void __launch_bounds__(512) glu_ln_kernel(
    const float* __restrict__ out_w, const float* __restrict__ out_b,
    const float* __restrict__ ln_w,  const float* __restrict__ ln_b,
    int layer) {
    extern __shared__ float sm[];
    float* Rsh = sm;                        // 256*64
    float* Wsh = sm + 16384;                // 32*512
    float* Ysh = sm + 16384 + 16384;        // 32*68
    float* Gsh = sm + 16384;                // 512*68 (phase B, overlaps Wsh/Ysh)
    __shared__ float redS[8][64];
    __shared__ float redQ[8][64];

    int b    = blockIdx.y;
    int pos0 = blockIdx.x * 64;
    int tid  = threadIdx.x;
    const float* wlay = out_w + (size_t)layer * 512 * HCH;

    // residual tile
#pragma unroll
    for (int k = 0; k < 8; k++) {
        int e  = tid + k * 512;
        int h  = e >> 4;
        int p4 = e & 15;
        float4 v = *(const float4*)(g_h + ((size_t)(b * HCH + h)) * LSEQ +
                                    pos0 + p4 * 4);
        *(float4*)&Rsh[h * 64 + p4 * 4] = v;
    }

    int tj = tid >> 3;   // j tile (8 consecutive j)
    int tp = tid & 7;    // pos tile (8 consecutive pos = 4 packed pairs)
    unsigned long long acc2[8][4];
#pragma unroll
    for (int r = 0; r < 8; r++)
#pragma unroll
        for (int c = 0; c < 4; c++) acc2[r][c] = 0ULL;

    for (int k0 = 0; k0 < HCH; k0 += 32) {
        __syncthreads();
        {
            const float4* wr = (const float4*)(wlay + (size_t)tid * HCH + k0);
#pragma unroll
            for (int q = 0; q < 8; q++) {
                float4 v = wr[q];
                Wsh[(q * 4 + 0) * 512 + tid] = v.x;
                Wsh[(q * 4 + 1) * 512 + tid] = v.y;
                Wsh[(q * 4 + 2) * 512 + tid] = v.z;
                Wsh[(q * 4 + 3) * 512 + tid] = v.w;
            }
        }
        {
            int kk = tid >> 4;
            int p4 = tid & 15;
            float4 v = *(const float4*)(g_y +
                                        ((size_t)(b * HCH + k0 + kk)) * LSEQ +
                                        pos0 + p4 * 4);
            *(float4*)&Ysh[kk * 68 + p4 * 4] = v;
        }
        __syncthreads();
#pragma unroll
        for (int kk = 0; kk < 32; kk++) {
            float4 a0 = *(const float4*)&Wsh[kk * 512 + tj * 8];
            float4 a1 = *(const float4*)&Wsh[kk * 512 + tj * 8 + 4];
            ulonglong2 b0 = *(const ulonglong2*)&Ysh[kk * 68 + tp * 8];
            ulonglong2 b1 = *(const ulonglong2*)&Ysh[kk * 68 + tp * 8 + 4];
            unsigned long long bv[4] = {b0.x, b0.y, b1.x, b1.y};
            float av[8] = {a0.x, a0.y, a0.z, a0.w, a1.x, a1.y, a1.z, a1.w};
#pragma unroll
            for (int r = 0; r < 8; r++) {
                unsigned long long ar = pack2(av[r], av[r]);
#pragma unroll
                for (int c = 0; c < 4; c++) fma2(acc2[r][c], ar, bv[c]);
            }
        }
    }
    __syncthreads();

    // bias + stage g into Gsh[j][pos]
#pragma unroll
    for (int r = 0; r < 8; r++) {
        int j = tj * 8 + r;
        float bias = __ldg(&out_b[layer * 512 + j]);
        float2 p0 = unpack2(acc2[r][0]);
        float2 p1 = unpack2(acc2[r][1]);
        float2 p2 = unpack2(acc2[r][2]);
        float2 p3 = unpack2(acc2[r][3]);
        float4 o0 = make_float4(p0.x + bias, p0.y + bias, p1.x + bias, p1.y + bias);
        float4 o1 = make_float4(p2.x + bias, p2.y + bias, p3.x + bias, p3.y + bias);
        *(float4*)&Gsh[j * 68 + tp * 8]     = o0;
        *(float4*)&Gsh[j * 68 + tp * 8 + 4] = o1;
    }
    __syncthreads();

    // GLU + residual + channel LayerNorm
    int grp = tid >> 6;
    int pos = tid & 63;
    float uv[32];
    float sum = 0.0f, sq = 0.0f;
#pragma unroll
    for (int r = 0; r < 32; r++) {
        int h = grp * 32 + r;
        float g1 = Gsh[h * 68 + pos];
        float g2 = Gsh[(h + 256) * 68 + pos];
        float sg = 1.0f / (1.0f + expf(-g2));
        float u  = fmaf(g1, sg, Rsh[h * 64 + pos]);
        uv[r] = u;
        sum += u;
        sq = fmaf(u, u, sq);
    }
    redS[grp][pos] = sum;
    redQ[grp][pos] = sq;
    __syncthreads();
    float tot = 0.0f, totq = 0.0f;
#pragma unroll
    for (int g8 = 0; g8 < 8; g8++) {
        tot  += redS[g8][pos];
        totq += redQ[g8][pos];
    }
    float mean = tot * (1.0f / 256.0f);
    float var  = fmaf(-mean, mean, totq * (1.0f / 256.0f));
    float rs   = rsqrtf(var + 1e-5f);
#pragma unroll
    for (int r = 0; r < 32; r++) {
        int h = grp * 32 + r;
        float w  = __ldg(&ln_w[layer * HCH + h]);
        float bb = __ldg(&ln_b[layer * HCH + h]);
        float val = fmaf((uv[r] - mean) * rs, w, bb);
        g_h[((size_t)(b * HCH + h)) * LSEQ + pos0 + pos] = val;
    }
}

// ---------------------------------------------------------------------------
// Decoder
// ---------------------------------------------------------------------------
__global__ void __launch_bounds__(256) decoder_kernel(
    const float* __restrict__ dec_w, const float* __restrict__ dec_b,
    float* __restrict__ out) {
    __shared__ float wsh[DOUT * HCH];
    __shared__ float bsh[DOUT];
    int b    = blockIdx.y;
    int pos0 = blockIdx.x * 256;
    int tid  = threadIdx.x;
    for (int e = tid; e < DOUT * HCH; e += 256) wsh[e] = dec_w[e];
    if (tid < DOUT) bsh[tid] = dec_b[tid];
    __syncthreads();

    float acc[DOUT];
#pragma unroll
    for (int o = 0; o < DOUT; o++) acc[o] = bsh[o];

    const float* hp = g_h + (size_t)b * HCH * LSEQ + pos0 + tid;
    for (int h = 0; h < HCH; h++) {
        float xv = hp[(size_t)h * LSEQ];
#pragma unroll
        for (int o = 0; o < DOUT; o++)
            acc[o] = fmaf(xv, wsh[o * HCH + h], acc[o]);
    }
    float* op = out + ((size_t)(b * LSEQ) + pos0 + tid) * DOUT;
#pragma unroll
    for (int o = 0; o < DOUT; o++) op[o] = acc[o];
}

// ---------------------------------------------------------------------------
extern "C" void kernel_launch(void* const* d_in, const int* in_sizes, int n_in,
                              void* d_out, int out_size) {
    const float* x          = (const float*)d_in[0];
    const float* enc_w      = (const float*)d_in[1];
    const float* enc_b      = (const float*)d_in[2];
    const float* log_dt     = (const float*)d_in[3];
    const float* log_A_real = (const float*)d_in[4];
    const float* A_imag     = (const float*)d_in[5];
    const float* C_re       = (const float*)d_in[6];
    const float* C_im       = (const float*)d_in[7];
    const float* Dv         = (const float*)d_in[8];
    const float* out_w      = (const float*)d_in[9];
    const float* out_b      = (const float*)d_in[10];
    const float* ln_w       = (const float*)d_in[11];
    const float* ln_b       = (const float*)d_in[12];
    const float* dec_w      = (const float*)d_in[13];
    const float* dec_b      = (const float*)d_in[14];
    float* out = (float*)d_out;

    size_t enc_smem = (size_t)(64 * HCH + 64 * 68) * sizeof(float);
    size_t glu_smem = (size_t)(16384 + 512 * 68) * sizeof(float);
    cudaFuncSetAttribute(encoder_kernel,
                         cudaFuncAttributeMaxDynamicSharedMemorySize,
                         (int)enc_smem);
    cudaFuncSetAttribute(glu_ln_kernel,
                         cudaFuncAttributeMaxDynamicSharedMemorySize,
                         (int)glu_smem);

    params_kernel<<<(NLAY * HCH * NST + 255) / 256, 256>>>(
        log_dt, log_A_real, A_imag, C_re, C_im);
    encoder_kernel<<<dim3(LSEQ / 64, NBATCH), 256, enc_smem>>>(x, enc_w, enc_b);
    for (int layer = 0; layer < NLAY; layer++) {
        scan_kernel<<<512, 256>>>(Dv, layer);
        glu_ln_kernel<<<dim3(LSEQ / 64, NBATCH), 512, glu_smem>>>(
            out_w, out_b, ln_w, ln_b, layer);
    }
    decoder_kernel<<<dim3(LSEQ / 256, NBATCH), 256>>>(dec_w, dec_b, out);
}

// round 4
// speedup vs baseline: 1.1467x; 1.1279x over previous
#include <cuda_runtime.h>
#include <cuda_bf16.h>
#include <math.h>
#include <stdint.h>

#define NBATCH 16
#define LSEQ   4096
#define DIN    64
#define HCH    256
#define NST    32
#define NLAY   4
#define DOUT   10

// ===========================================================================
// Base-ISA PTX helpers (sm_80+ features only — the bench builds compute_103,
// so no tcgen05 / 'a'-suffix features are available)
// ===========================================================================
__device__ __forceinline__ uint32_t smem_u32(const void* p) {
    uint32_t a;
    asm("{ .reg .u64 t; cvta.to.shared.u64 t, %1; cvt.u32.u64 %0, t; }"
        : "=r"(a) : "l"(p));
    return a;
}
__device__ __forceinline__ void cp16(uint32_t dst, const void* src) {
    asm volatile("cp.async.cg.shared.global [%0], [%1], 16;"
                 :: "r"(dst), "l"(src));
}
#define CP_COMMIT() asm volatile("cp.async.commit_group;" ::: "memory")
#define CP_WAIT0()  asm volatile("cp.async.wait_group 0;" ::: "memory")
#define CP_WAIT1()  asm volatile("cp.async.wait_group 1;" ::: "memory")

__device__ __forceinline__ void ldsm4(uint32_t* r, uint32_t addr) {
    asm volatile("ldmatrix.sync.aligned.m8n8.x4.shared.b16 {%0,%1,%2,%3}, [%4];"
                 : "=r"(r[0]), "=r"(r[1]), "=r"(r[2]), "=r"(r[3]) : "r"(addr));
}
__device__ __forceinline__ void mma_bf16(float* d, const uint32_t* a,
                                         uint32_t b0, uint32_t b1) {
    asm volatile(
        "mma.sync.aligned.m16n8k16.row.col.f32.bf16.bf16.f32 "
        "{%0,%1,%2,%3}, {%4,%5,%6,%7}, {%8,%9}, {%0,%1,%2,%3};"
        : "+f"(d[0]), "+f"(d[1]), "+f"(d[2]), "+f"(d[3])
        : "r"(a[0]), "r"(a[1]), "r"(a[2]), "r"(a[3]), "r"(b0), "r"(b1));
}

// ===========================================================================
// Packed fp32x2 helpers (encoder)
// ===========================================================================
__device__ __forceinline__ unsigned long long pack2(float x, float y) {
    unsigned long long r;
    asm("mov.b64 %0, {%1, %2};" : "=l"(r) : "f"(x), "f"(y));
    return r;
}
__device__ __forceinline__ void fma2(unsigned long long& d,
                                     unsigned long long a,
                                     unsigned long long b) {
    asm("fma.rn.f32x2 %0, %1, %2, %0;" : "+l"(d) : "l"(a), "l"(b));
}
__device__ __forceinline__ float2 unpack2(unsigned long long v) {
    float2 r;
    asm("mov.b64 {%0, %1}, %2;" : "=f"(r.x), "=f"(r.y) : "l"(v));
    return r;
}

// ===========================================================================
// Device scratch
// ===========================================================================
__device__ float g_h[NBATCH * HCH * LSEQ];                       // (B,H,L)
__device__ float g_g[(size_t)NBATCH * LSEQ * 512];               // GEMM out (row, 512)
__device__ __nv_bfloat16 g_yth[(size_t)NBATCH * LSEQ * HCH];     // y^T hi
__device__ __nv_bfloat16 g_ytl[(size_t)NBATCH * LSEQ * HCH];     // y^T lo
__device__ __nv_bfloat16 g_wh[NLAY * 512 * HCH];                 // out_w hi
__device__ __nv_bfloat16 g_wl[NLAY * 512 * HCH];                 // out_w lo
__device__ float g_par[NLAY][4][HCH * NST];

// ===========================================================================
// SSM parameter precompute
// ===========================================================================
__global__ void params_kernel(const float* __restrict__ log_dt,
                              const float* __restrict__ log_A_real,
                              const float* __restrict__ A_imag,
                              const float* __restrict__ C_re,
                              const float* __restrict__ C_im) {
    int idx = blockIdx.x * blockDim.x + threadIdx.x;
    if (idx >= NLAY * HCH * NST) return;
    int layer = idx / (HCH * NST);
    int hn    = idx - layer * (HCH * NST);
    int h     = hn / NST;

    float dt  = expf(log_dt[layer * HCH + h]);
    float Are = -expf(log_A_real[idx]);
    float Aim = A_imag[idx];
    float dre = Are * dt;
    float dimg = Aim * dt;

    float sy, cy;
    sincosf(dimg, &sy, &cy);
    float em1 = expm1f(dre);
    float ex  = em1 + 1.0f;
    float wre = ex * cy;
    float wim = ex * sy;
    float emr = fmaf(em1, cy, cy - 1.0f);
    float emi = ex * sy;

    float inv = 1.0f / fmaf(Are, Are, Aim * Aim);
    float tre = fmaf(emr, Are, emi * Aim) * inv;
    float tim = fmaf(emi, Are, -emr * Aim) * inv;

    float cre = C_re[idx], cim = C_im[idx];
    float ctre = fmaf(cre, tre, -cim * tim);
    float ctim = fmaf(cre, tim, cim * tre);

    g_par[layer][0][hn] = wre;
    g_par[layer][1][hn] = wim;
    g_par[layer][2][hn] = 2.0f * ctre;
    g_par[layer][3][hn] = -2.0f * ctim;
}

// ===========================================================================
// out_w bf16 hi/lo split (once)
// ===========================================================================
__global__ void wsplit_kernel(const float* __restrict__ out_w) {
    int idx = blockIdx.x * blockDim.x + threadIdx.x;
    if (idx >= NLAY * 512 * HCH) return;
    float w = out_w[idx];
    __nv_bfloat16 hi = __float2bfloat16(w);
    g_wh[idx] = hi;
    g_wl[idx] = __float2bfloat16(w - __bfloat162float(hi));
}

// ===========================================================================
// Encoder
// ===========================================================================
__global__ void __launch_bounds__(256) encoder_kernel(
    const float* __restrict__ x,
    const float* __restrict__ enc_w,
    const float* __restrict__ enc_b) {
    extern __shared__ float sm[];
    float* Wsh = sm;               // [64][256]
    float* Xsh = sm + 64 * HCH;    // [64][68]

    int b    = blockIdx.y;
    int pos0 = blockIdx.x * 64;
    int tid  = threadIdx.x;

    {
        const float4* wrow = (const float4*)(enc_w + (size_t)tid * DIN);
#pragma unroll
        for (int q = 0; q < 16; q++) {
            float4 v = wrow[q];
            Wsh[(q * 4 + 0) * HCH + tid] = v.x;
            Wsh[(q * 4 + 1) * HCH + tid] = v.y;
            Wsh[(q * 4 + 2) * HCH + tid] = v.z;
            Wsh[(q * 4 + 3) * HCH + tid] = v.w;
        }
    }
    {
#pragma unroll
        for (int k = 0; k < 4; k++) {
            int e  = tid + k * 256;
            int l  = e >> 4;
            int i4 = e & 15;
            const float4* xr =
                (const float4*)(x + ((size_t)(b * LSEQ) + pos0 + l) * DIN);
            float4 v = xr[i4];
            Xsh[(i4 * 4 + 0) * 68 + l] = v.x;
            Xsh[(i4 * 4 + 1) * 68 + l] = v.y;
            Xsh[(i4 * 4 + 2) * 68 + l] = v.z;
            Xsh[(i4 * 4 + 3) * 68 + l] = v.w;
        }
    }
    __syncthreads();

    int th = tid >> 3;
    int tl = tid & 7;
    unsigned long long acc2[8][4];
#pragma unroll
    for (int r = 0; r < 8; r++)
#pragma unroll
        for (int c = 0; c < 4; c++) acc2[r][c] = 0ULL;

    for (int i = 0; i < DIN; i++) {
        float4 a0 = *(const float4*)&Wsh[i * HCH + th * 8];
        float4 a1 = *(const float4*)&Wsh[i * HCH + th * 8 + 4];
        ulonglong2 b0 = *(const ulonglong2*)&Xsh[i * 68 + tl * 8];
        ulonglong2 b1 = *(const ulonglong2*)&Xsh[i * 68 + tl * 8 + 4];
        unsigned long long bv[4] = {b0.x, b0.y, b1.x, b1.y};
        float av[8] = {a0.x, a0.y, a0.z, a0.w, a1.x, a1.y, a1.z, a1.w};
#pragma unroll
        for (int r = 0; r < 8; r++) {
            unsigned long long ar = pack2(av[r], av[r]);
#pragma unroll
            for (int c = 0; c < 4; c++) fma2(acc2[r][c], ar, bv[c]);
        }
    }

#pragma unroll
    for (int r = 0; r < 8; r++) {
        int h = th * 8 + r;
        float bias = __ldg(&enc_b[h]);
        float* dst = g_h + ((size_t)(b * HCH + h)) * LSEQ + pos0 + tl * 8;
        float2 p0 = unpack2(acc2[r][0]);
        float2 p1 = unpack2(acc2[r][1]);
        float2 p2 = unpack2(acc2[r][2]);
        float2 p3 = unpack2(acc2[r][3]);
        float4 o0 = make_float4(p0.x + bias, p0.y + bias, p1.x + bias, p1.y + bias);
        float4 o1 = make_float4(p2.x + bias, p2.y + bias, p3.x + bias, p3.y + bias);
        ((float4*)dst)[0] = o0;
        ((float4*)dst)[1] = o1;
    }
}

// ===========================================================================
// SSM scan + D-skip + GELU -> transposed bf16 hi/lo output [b][l][h].
// ===========================================================================
__global__ void __launch_bounds__(256) scan_kernel(const float* __restrict__ Dvec,
                                                   int layer) {
    __shared__ float sh[8][32][33];
    __shared__ __align__(16) __nv_bfloat16 tb_h[2][32][8];
    __shared__ __align__(16) __nv_bfloat16 tb_l[2][32][8];

    int tid  = threadIdx.x;
    int wid  = tid >> 5;
    int lane = tid & 31;
    int c0   = blockIdx.x * 8;
    int c    = c0 + wid;
    int b0   = c0 >> 8;
    int h0   = c0 & (HCH - 1);
    int h    = c & (HCH - 1);

    const float* par = &g_par[layer][0][0];
    float wre = par[0 * (HCH * NST) + h * NST + lane];
    float wim = par[1 * (HCH * NST) + h * NST + lane];
    float ca  = par[2 * (HCH * NST) + h * NST + lane];
    float cb  = par[3 * (HCH * NST) + h * NST + lane];
    float Dh  = __ldg(&Dvec[layer * HCH + h]);

    const float* zin = g_h + (size_t)c * LSEQ;
    float (*S)[33] = sh[wid];

    float sre = 0.0f, sim = 0.0f;
    for (int l0 = 0; l0 < LSEQ; l0 += 32) {
        float zv = zin[l0 + lane];
#pragma unroll
        for (int t = 0; t < 32; t++) {
            float z  = __shfl_sync(0xffffffffu, zv, t);
            float nr = fmaf(wre, sre, z);
            nr       = fmaf(-wim, sim, nr);
            float ni = fmaf(wim, sre, wre * sim);
            sre = nr;
            sim = ni;
            S[lane][t] = fmaf(ca, sre, cb * sim);
        }
        __syncwarp();
        float acc = 0.0f;
#pragma unroll
        for (int n = 0; n < 32; n++) acc += S[n][lane];
        float yv = fmaf(Dh, zv, acc);
        float u  = 0.7978845608028654f * fmaf(0.044715f, yv * yv * yv, yv);
        float gv = 0.5f * yv * (1.0f + tanhf(u));

        int buf = (l0 >> 5) & 1;
        __nv_bfloat16 bh = __float2bfloat16(gv);
        __nv_bfloat16 bl = __float2bfloat16(gv - __bfloat162float(bh));
        tb_h[buf][lane][wid] = bh;
        tb_l[buf][lane][wid] = bl;
        __syncthreads();
        if (tid < 32) {
            uint4 v = *(const uint4*)&tb_h[buf][tid][0];
            *(uint4*)(g_yth + ((size_t)(b0 * LSEQ) + l0 + tid) * HCH + h0) = v;
        } else if (tid < 64) {
            int l = tid - 32;
            uint4 v = *(const uint4*)&tb_l[buf][l][0];
            *(uint4*)(g_ytl + ((size_t)(b0 * LSEQ) + l0 + l) * HCH + h0) = v;
        }
    }
}

// ===========================================================================
// HMMA GEMM: g[row, j] = Y^T[row, k] @ W[j, k]^T, bf16 3-term split, fp32 acc.
// CTA = 128 rows x 128 j, 8 warps (warp tile 32x64). k chunks of 64,
// cp.async double-buffered. SMEM tile stride 144B (conflict-free ldmatrix).
// ===========================================================================
#define TILE_B   18432              // 128 rows * 144B
#define BUF_B    (4 * TILE_B)       // Ah, Al, Bh, Bl
#define GEMM_SMEM (2 * BUF_B)       // 147456

__global__ void __launch_bounds__(256) gemm_kernel(int layer) {
    extern __shared__ char smem[];
    int tid  = threadIdx.x;
    int wid  = tid >> 5;
    int lane = tid & 31;
    int row0 = blockIdx.x * 128;          // in [0, B*L)
    int j0   = blockIdx.y * 128;

    const __nv_bfloat16* Ah = g_yth + (size_t)row0 * HCH;
    const __nv_bfloat16* Al = g_ytl + (size_t)row0 * HCH;
    const __nv_bfloat16* Bh = g_wh + ((size_t)layer * 512 + j0) * HCH;
    const __nv_bfloat16* Bl = g_wl + ((size_t)layer * 512 + j0) * HCH;

    uint32_t sb = smem_u32(smem);

    int seg = tid & 7;        // 16B segment within 128B row
    int rr0 = tid >> 3;       // 0..31

    float acc[2][8][4];
#pragma unroll
    for (int mt = 0; mt < 2; mt++)
#pragma unroll
        for (int nt = 0; nt < 8; nt++)
#pragma unroll
            for (int e = 0; e < 4; e++) acc[mt][nt][e] = 0.0f;

    int wm = wid >> 1;        // 0..3  (32-row group)
    int wn = wid & 1;         // 0..1  (64-j group)

    // stage chunk 0
    {
        uint32_t base = sb;
#pragma unroll
        for (int i = 0; i < 4; i++) {
            int row = rr0 + i * 32;
            uint32_t d = base + row * 144 + seg * 16;
            int go = row * HCH + seg * 8;
            cp16(d,              Ah + go);
            cp16(d + TILE_B,     Al + go);
            cp16(d + 2 * TILE_B, Bh + go);
            cp16(d + 3 * TILE_B, Bl + go);
        }
        CP_COMMIT();
    }

    int buf = 0;
    for (int ch = 0; ch < 4; ch++) {
        if (ch < 3) {
            uint32_t base = sb + (buf ^ 1) * BUF_B;
            int k0 = (ch + 1) * 64;
#pragma unroll
            for (int i = 0; i < 4; i++) {
                int row = rr0 + i * 32;
                uint32_t d = base + row * 144 + seg * 16;
                int go = row * HCH + k0 + seg * 8;
                cp16(d,              Ah + go);
                cp16(d + TILE_B,     Al + go);
                cp16(d + 2 * TILE_B, Bh + go);
                cp16(d + 3 * TILE_B, Bl + go);
            }
            CP_COMMIT();
            CP_WAIT1();
        } else {
            CP_WAIT0();
        }
        __syncthreads();

        uint32_t cbase = sb + buf * BUF_B;
#pragma unroll
        for (int pass = 0; pass < 3; pass++) {
            uint32_t aoff = cbase + (pass == 2 ? TILE_B : 0);
            uint32_t boff = cbase + (pass == 1 ? 3 * TILE_B : 2 * TILE_B);
#pragma unroll
            for (int ks = 0; ks < 4; ks++) {
                uint32_t colb = ks * 32 + (lane >> 4) * 16;
                uint32_t afrag[2][4];
                uint32_t a0 = aoff + (wm * 32 + (lane & 15)) * 144 + colb;
                ldsm4(afrag[0], a0);
                ldsm4(afrag[1], a0 + 16 * 144);
                uint32_t bfrag[4][4];
#pragma unroll
                for (int np = 0; np < 4; np++) {
                    uint32_t ba = boff +
                        (wn * 64 + np * 16 + (lane & 15)) * 144 + colb;
                    ldsm4(bfrag[np], ba);
                }
#pragma unroll
                for (int mt = 0; mt < 2; mt++)
#pragma unroll
                    for (int nt = 0; nt < 8; nt++) {
                        const uint32_t* bf = bfrag[nt >> 1];
                        uint32_t b0 = (nt & 1) ? bf[1] : bf[0];
                        uint32_t b1 = (nt & 1) ? bf[3] : bf[2];
                        mma_bf16(acc[mt][nt], afrag[mt], b0, b1);
                    }
            }
        }
        __syncthreads();
        buf ^= 1;
    }

    // store
    float* gout = g_g + (size_t)row0 * 512 + j0;
#pragma unroll
    for (int mt = 0; mt < 2; mt++)
#pragma unroll
        for (int nt = 0; nt < 8; nt++) {
            int r = wm * 32 + mt * 16 + (lane >> 2);
            int c = wn * 64 + nt * 8 + (lane & 3) * 2;
            float2 v0 = make_float2(acc[mt][nt][0], acc[mt][nt][1]);
            float2 v1 = make_float2(acc[mt][nt][2], acc[mt][nt][3]);
            *(float2*)&gout[(size_t)r * 512 + c]       = v0;
            *(float2*)&gout[(size_t)(r + 8) * 512 + c] = v1;
        }
}

// ===========================================================================
// Epilogue: bias + GLU + residual + channel LayerNorm. Per 128-row tile.
// ===========================================================================
#define EPI_SMEM (128 * 257 * 4)

__global__ void __launch_bounds__(512) glu_ln_kernel(
    const float* __restrict__ out_b, const float* __restrict__ ln_w,
    const float* __restrict__ ln_b, int layer) {
    extern __shared__ float usm[];  // [128][257]
    __shared__ float s_ob[512];
    __shared__ float s_lnw[HCH];
    __shared__ float s_lnb[HCH];
    __shared__ float s_mu[128];
    __shared__ float s_rs[128];

    int tid  = threadIdx.x;
    int row0 = blockIdx.x * 128;
    int b    = row0 >> 12;
    int pos0 = row0 & (LSEQ - 1);

    s_ob[tid] = __ldg(&out_b[layer * 512 + tid]);
    if (tid < HCH) {
        s_lnw[tid] = __ldg(&ln_w[layer * HCH + tid]);
        s_lnb[tid] = __ldg(&ln_b[layer * HCH + tid]);
    }
    __syncthreads();

    const float* gg = g_g + (size_t)row0 * 512;
    // phase A: u = (g1+b1) * sigmoid(g2+b2)
#pragma unroll 4
    for (int it = 0; it < 64; it++) {
        int flat = tid + it * 512;
        int p = flat >> 8;
        int h = flat & 255;
        float g1 = gg[(size_t)p * 512 + h] + s_ob[h];
        float g2 = gg[(size_t)p * 512 + 256 + h] + s_ob[256 + h];
        usm[p * 257 + h] = g1 / (1.0f + expf(-g2));
    }
    __syncthreads();

    // phase B: + residual
    const float* resb = g_h + (size_t)(b * HCH) * LSEQ + pos0;
#pragma unroll 4
    for (int it = 0; it < 64; it++) {
        int flat = tid + it * 512;
        int h = flat >> 7;
        int p = flat & 127;
        usm[p * 257 + h] += resb[(size_t)h * LSEQ + p];
    }
    __syncthreads();

    // phase C: per-pos mean/var over 256 channels
    {
        int w = tid >> 5, lane = tid & 31;
#pragma unroll
        for (int i = 0; i < 8; i++) {
            int pos = w * 8 + i;
            float s = 0.0f, q = 0.0f;
#pragma unroll
            for (int r = 0; r < 8; r++) {
                float v = usm[pos * 257 + lane + r * 32];
                s += v;
                q = fmaf(v, v, q);
            }
#pragma unroll
            for (int off = 16; off > 0; off >>= 1) {
                s += __shfl_xor_sync(0xffffffffu, s, off);
                q += __shfl_xor_sync(0xffffffffu, q, off);
            }
            if (lane == 0) {
                float m = s * (1.0f / 256.0f);
                s_mu[pos] = m;
                s_rs[pos] = rsqrtf(fmaf(-m, m, q * (1.0f / 256.0f)) + 1e-5f);
            }
        }
    }
    __syncthreads();

    // phase D: normalize + write back to g_h
    float* outp = g_h + (size_t)(b * HCH) * LSEQ + pos0;
#pragma unroll 4
    for (int it = 0; it < 64; it++) {
        int flat = tid + it * 512;
        int h = flat >> 7;
        int p = flat & 127;
        float u = usm[p * 257 + h];
        outp[(size_t)h * LSEQ + p] =
            fmaf((u - s_mu[p]) * s_rs[p], s_lnw[h], s_lnb[h]);
    }
}

// ===========================================================================
// Decoder
// ===========================================================================
__global__ void __launch_bounds__(256) decoder_kernel(
    const float* __restrict__ dec_w, const float* __restrict__ dec_b,
    float* __restrict__ out) {
    __shared__ float wsh[DOUT * HCH];
    __shared__ float bsh[DOUT];
    int b    = blockIdx.y;
    int pos0 = blockIdx.x * 256;
    int tid  = threadIdx.x;
    for (int e = tid; e < DOUT * HCH; e += 256) wsh[e] = dec_w[e];
    if (tid < DOUT) bsh[tid] = dec_b[tid];
    __syncthreads();

    float acc[DOUT];
#pragma unroll
    for (int o = 0; o < DOUT; o++) acc[o] = bsh[o];

    const float* hp = g_h + (size_t)b * HCH * LSEQ + pos0 + tid;
    for (int h = 0; h < HCH; h++) {
        float xv = hp[(size_t)h * LSEQ];
#pragma unroll
        for (int o = 0; o < DOUT; o++)
            acc[o] = fmaf(xv, wsh[o * HCH + h], acc[o]);
    }
    float* op = out + ((size_t)(b * LSEQ) + pos0 + tid) * DOUT;
#pragma unroll
    for (int o = 0; o < DOUT; o++) op[o] = acc[o];
}

// ===========================================================================
extern "C" void kernel_launch(void* const* d_in, const int* in_sizes, int n_in,
                              void* d_out, int out_size) {
    const float* x          = (const float*)d_in[0];
    const float* enc_w      = (const float*)d_in[1];
    const float* enc_b      = (const float*)d_in[2];
    const float* log_dt     = (const float*)d_in[3];
    const float* log_A_real = (const float*)d_in[4];
    const float* A_imag     = (const float*)d_in[5];
    const float* C_re       = (const float*)d_in[6];
    const float* C_im       = (const float*)d_in[7];
    const float* Dv         = (const float*)d_in[8];
    const float* out_w      = (const float*)d_in[9];
    const float* out_b      = (const float*)d_in[10];
    const float* ln_w       = (const float*)d_in[11];
    const float* ln_b       = (const float*)d_in[12];
    const float* dec_w      = (const float*)d_in[13];
    const float* dec_b      = (const float*)d_in[14];
    float* out = (float*)d_out;

    size_t enc_smem = (size_t)(64 * HCH + 64 * 68) * sizeof(float);
    cudaFuncSetAttribute(encoder_kernel,
                         cudaFuncAttributeMaxDynamicSharedMemorySize,
                         (int)enc_smem);
    cudaFuncSetAttribute(gemm_kernel,
                         cudaFuncAttributeMaxDynamicSharedMemorySize,
                         GEMM_SMEM);
    cudaFuncSetAttribute(glu_ln_kernel,
                         cudaFuncAttributeMaxDynamicSharedMemorySize,
                         EPI_SMEM);

    params_kernel<<<(NLAY * HCH * NST + 255) / 256, 256>>>(
        log_dt, log_A_real, A_imag, C_re, C_im);
    wsplit_kernel<<<(NLAY * 512 * HCH + 255) / 256, 256>>>(out_w);
    encoder_kernel<<<dim3(LSEQ / 64, NBATCH), 256, enc_smem>>>(x, enc_w, enc_b);
    for (int layer = 0; layer < NLAY; layer++) {
        scan_kernel<<<512, 256>>>(Dv, layer);
        gemm_kernel<<<dim3(NBATCH * LSEQ / 128, 4), 256, GEMM_SMEM>>>(layer);
        glu_ln_kernel<<<NBATCH * LSEQ / 128, 512, EPI_SMEM>>>(
            out_b, ln_w, ln_b, layer);
    }
    decoder_kernel<<<dim3(LSEQ / 256, NBATCH), 256>>>(dec_w, dec_b, out);
}

// round 5
// speedup vs baseline: 1.2224x; 1.0660x over previous
#include <cuda_runtime.h>
#include <cuda_bf16.h>
#include <math.h>
#include <stdint.h>

#define NBATCH 16
#define LSEQ   4096
#define DIN    64
#define HCH    256
#define NST    32
#define NLAY   4
#define DOUT   10

// ===========================================================================
// Base-ISA PTX helpers (compute_103 base — no tcgen05 / 'a'-suffix features)
// ===========================================================================
__device__ __forceinline__ uint32_t smem_u32(const void* p) {
    uint32_t a;
    asm("{ .reg .u64 t; cvta.to.shared.u64 t, %1; cvt.u32.u64 %0, t; }"
        : "=r"(a) : "l"(p));
    return a;
}
__device__ __forceinline__ void cp16(uint32_t dst, const void* src) {
    asm volatile("cp.async.cg.shared.global [%0], [%1], 16;"
                 :: "r"(dst), "l"(src));
}
#define CP_COMMIT() asm volatile("cp.async.commit_group;" ::: "memory")
#define CP_WAIT0()  asm volatile("cp.async.wait_group 0;" ::: "memory")
#define CP_WAIT1()  asm volatile("cp.async.wait_group 1;" ::: "memory")

__device__ __forceinline__ void ldsm4(uint32_t* r, uint32_t addr) {
    asm volatile("ldmatrix.sync.aligned.m8n8.x4.shared.b16 {%0,%1,%2,%3}, [%4];"
                 : "=r"(r[0]), "=r"(r[1]), "=r"(r[2]), "=r"(r[3]) : "r"(addr));
}
__device__ __forceinline__ void ldsm4t(uint32_t* r, uint32_t addr) {
    asm volatile("ldmatrix.sync.aligned.m8n8.x4.trans.shared.b16 {%0,%1,%2,%3}, [%4];"
                 : "=r"(r[0]), "=r"(r[1]), "=r"(r[2]), "=r"(r[3]) : "r"(addr));
}
__device__ __forceinline__ void mma_bf16(float* d, const uint32_t* a,
                                         uint32_t b0, uint32_t b1) {
    asm volatile(
        "mma.sync.aligned.m16n8k16.row.col.f32.bf16.bf16.f32 "
        "{%0,%1,%2,%3}, {%4,%5,%6,%7}, {%8,%9}, {%0,%1,%2,%3};"
        : "+f"(d[0]), "+f"(d[1]), "+f"(d[2]), "+f"(d[3])
        : "r"(a[0]), "r"(a[1]), "r"(a[2]), "r"(a[3]), "r"(b0), "r"(b1));
}

// ===========================================================================
// Packed fp32x2 helpers (encoder)
// ===========================================================================
__device__ __forceinline__ unsigned long long pack2(float x, float y) {
    unsigned long long r;
    asm("mov.b64 %0, {%1, %2};" : "=l"(r) : "f"(x), "f"(y));
    return r;
}
__device__ __forceinline__ void fma2(unsigned long long& d,
                                     unsigned long long a,
                                     unsigned long long b) {
    asm("fma.rn.f32x2 %0, %1, %2, %0;" : "+l"(d) : "l"(a), "l"(b));
}
__device__ __forceinline__ float2 unpack2(unsigned long long v) {
    float2 r;
    asm("mov.b64 {%0, %1}, %2;" : "=f"(r.x), "=f"(r.y) : "l"(v));
    return r;
}

// ===========================================================================
// Device scratch
// ===========================================================================
__device__ float g_h[NBATCH * HCH * LSEQ];                       // (B,H,L)
__device__ float g_g[(size_t)NBATCH * LSEQ * 512];               // GEMM out (row, 512)
__device__ __nv_bfloat16 g_yh[(size_t)NBATCH * HCH * LSEQ];      // y hi, [c][l]
__device__ __nv_bfloat16 g_yl[(size_t)NBATCH * HCH * LSEQ];      // y lo, [c][l]
__device__ __nv_bfloat16 g_wh[NLAY * 512 * HCH];                 // out_w hi
__device__ __nv_bfloat16 g_wl[NLAY * 512 * HCH];                 // out_w lo
__device__ float g_par[NLAY][4][HCH * NST];

// ===========================================================================
// SSM parameter precompute
// ===========================================================================
__global__ void params_kernel(const float* __restrict__ log_dt,
                              const float* __restrict__ log_A_real,
                              const float* __restrict__ A_imag,
                              const float* __restrict__ C_re,
                              const float* __restrict__ C_im) {
    int idx = blockIdx.x * blockDim.x + threadIdx.x;
    if (idx >= NLAY * HCH * NST) return;
    int layer = idx / (HCH * NST);
    int hn    = idx - layer * (HCH * NST);
    int h     = hn / NST;

    float dt  = expf(log_dt[layer * HCH + h]);
    float Are = -expf(log_A_real[idx]);
    float Aim = A_imag[idx];
    float dre = Are * dt;
    float dimg = Aim * dt;

    float sy, cy;
    sincosf(dimg, &sy, &cy);
    float em1 = expm1f(dre);
    float ex  = em1 + 1.0f;
    float wre = ex * cy;
    float wim = ex * sy;
    float emr = fmaf(em1, cy, cy - 1.0f);
    float emi = ex * sy;

    float inv = 1.0f / fmaf(Are, Are, Aim * Aim);
    float tre = fmaf(emr, Are, emi * Aim) * inv;
    float tim = fmaf(emi, Are, -emr * Aim) * inv;

    float cre = C_re[idx], cim = C_im[idx];
    float ctre = fmaf(cre, tre, -cim * tim);
    float ctim = fmaf(cre, tim, cim * tre);

    g_par[layer][0][hn] = wre;
    g_par[layer][1][hn] = wim;
    g_par[layer][2][hn] = 2.0f * ctre;
    g_par[layer][3][hn] = -2.0f * ctim;
}

// ===========================================================================
// out_w bf16 hi/lo split (once)
// ===========================================================================
__global__ void wsplit_kernel(const float* __restrict__ out_w) {
    int idx = blockIdx.x * blockDim.x + threadIdx.x;
    if (idx >= NLAY * 512 * HCH) return;
    float w = out_w[idx];
    __nv_bfloat16 hi = __float2bfloat16(w);
    g_wh[idx] = hi;
    g_wl[idx] = __float2bfloat16(w - __bfloat162float(hi));
}

// ===========================================================================
// Encoder
// ===========================================================================
__global__ void __launch_bounds__(256) encoder_kernel(
    const float* __restrict__ x,
    const float* __restrict__ enc_w,
    const float* __restrict__ enc_b) {
    extern __shared__ float sm[];
    float* Wsh = sm;               // [64][256]
    float* Xsh = sm + 64 * HCH;    // [64][68]

    int b    = blockIdx.y;
    int pos0 = blockIdx.x * 64;
    int tid  = threadIdx.x;

    {
        const float4* wrow = (const float4*)(enc_w + (size_t)tid * DIN);
#pragma unroll
        for (int q = 0; q < 16; q++) {
            float4 v = wrow[q];
            Wsh[(q * 4 + 0) * HCH + tid] = v.x;
            Wsh[(q * 4 + 1) * HCH + tid] = v.y;
            Wsh[(q * 4 + 2) * HCH + tid] = v.z;
            Wsh[(q * 4 + 3) * HCH + tid] = v.w;
        }
    }
    {
#pragma unroll
        for (int k = 0; k < 4; k++) {
            int e  = tid + k * 256;
            int l  = e >> 4;
            int i4 = e & 15;
            const float4* xr =
                (const float4*)(x + ((size_t)(b * LSEQ) + pos0 + l) * DIN);
            float4 v = xr[i4];
            Xsh[(i4 * 4 + 0) * 68 + l] = v.x;
            Xsh[(i4 * 4 + 1) * 68 + l] = v.y;
            Xsh[(i4 * 4 + 2) * 68 + l] = v.z;
            Xsh[(i4 * 4 + 3) * 68 + l] = v.w;
        }
    }
    __syncthreads();

    int th = tid >> 3;
    int tl = tid & 7;
    unsigned long long acc2[8][4];
#pragma unroll
    for (int r = 0; r < 8; r++)
#pragma unroll
        for (int c = 0; c < 4; c++) acc2[r][c] = 0ULL;

    for (int i = 0; i < DIN; i++) {
        float4 a0 = *(const float4*)&Wsh[i * HCH + th * 8];
        float4 a1 = *(const float4*)&Wsh[i * HCH + th * 8 + 4];
        ulonglong2 b0 = *(const ulonglong2*)&Xsh[i * 68 + tl * 8];
        ulonglong2 b1 = *(const ulonglong2*)&Xsh[i * 68 + tl * 8 + 4];
        unsigned long long bv[4] = {b0.x, b0.y, b1.x, b1.y};
        float av[8] = {a0.x, a0.y, a0.z, a0.w, a1.x, a1.y, a1.z, a1.w};
#pragma unroll
        for (int r = 0; r < 8; r++) {
            unsigned long long ar = pack2(av[r], av[r]);
#pragma unroll
            for (int c = 0; c < 4; c++) fma2(acc2[r][c], ar, bv[c]);
        }
    }

#pragma unroll
    for (int r = 0; r < 8; r++) {
        int h = th * 8 + r;
        float bias = __ldg(&enc_b[h]);
        float* dst = g_h + ((size_t)(b * HCH + h)) * LSEQ + pos0 + tl * 8;
        float2 p0 = unpack2(acc2[r][0]);
        float2 p1 = unpack2(acc2[r][1]);
        float2 p2 = unpack2(acc2[r][2]);
        float2 p3 = unpack2(acc2[r][3]);
        float4 o0 = make_float4(p0.x + bias, p0.y + bias, p1.x + bias, p1.y + bias);
        float4 o1 = make_float4(p2.x + bias, p2.y + bias, p3.x + bias, p3.y + bias);
        ((float4*)dst)[0] = o0;
        ((float4*)dst)[1] = o1;
    }
}

// ===========================================================================
// SSM scan + D-skip + GELU -> bf16 hi/lo in natural [c][l] layout.
// One warp per channel; no block-level syncs (GEMM transposes via ldmatrix.trans).
// gelu_tanh(y) == y * sigmoid(2u), computed with __expf.
// ===========================================================================
__global__ void __launch_bounds__(256) scan_kernel(const float* __restrict__ Dvec,
                                                   int layer) {
    __shared__ float sh[8][32][33];
    int tid  = threadIdx.x;
    int wid  = tid >> 5;
    int lane = tid & 31;
    int c    = blockIdx.x * 8 + wid;
    int h    = c & (HCH - 1);

    const float* par = &g_par[layer][0][0];
    float wre = par[0 * (HCH * NST) + h * NST + lane];
    float wim = par[1 * (HCH * NST) + h * NST + lane];
    float ca  = par[2 * (HCH * NST) + h * NST + lane];
    float cb  = par[3 * (HCH * NST) + h * NST + lane];
    float Dh  = __ldg(&Dvec[layer * HCH + h]);

    const float* zin = g_h + (size_t)c * LSEQ;
    __nv_bfloat16* yh = g_yh + (size_t)c * LSEQ;
    __nv_bfloat16* yl = g_yl + (size_t)c * LSEQ;
    float (*S)[33] = sh[wid];

    float sre = 0.0f, sim = 0.0f;
    float zv = zin[lane];
    for (int l0 = 0; l0 < LSEQ; l0 += 32) {
        float zn = (l0 + 32 < LSEQ) ? zin[l0 + 32 + lane] : 0.0f;
#pragma unroll
        for (int t = 0; t < 32; t++) {
            float z  = __shfl_sync(0xffffffffu, zv, t);
            float nr = fmaf(wre, sre, z);
            nr       = fmaf(-wim, sim, nr);
            float ni = fmaf(wim, sre, wre * sim);
            sre = nr;
            sim = ni;
            S[lane][t] = fmaf(ca, sre, cb * sim);
        }
        __syncwarp();
        float acc = 0.0f;
#pragma unroll
        for (int n = 0; n < 32; n++) acc += S[n][lane];
        float yv = fmaf(Dh, zv, acc);
        float u  = 0.7978845608028654f * fmaf(0.044715f, yv * yv * yv, yv);
        float gv = yv / (1.0f + __expf(-2.0f * u));
        __nv_bfloat16 bh = __float2bfloat16(gv);
        __nv_bfloat16 bl = __float2bfloat16(gv - __bfloat162float(bh));
        yh[l0 + lane] = bh;
        yl[l0 + lane] = bl;
        __syncwarp();
        zv = zn;
    }
}

// ===========================================================================
// HMMA GEMM: g[row, j] = Y[k, row] (trans via ldmatrix.trans) @ W[j, k]^T.
// bf16 3-term split, fp32 acc. CTA = 128 rows x 128 j, 8 warps (32x64 tiles),
// k chunks of 64, cp.async double-buffered.
// A tile: 64 k-rows x 128 l cols bf16, stride 272B (conflict-free trans ldsm).
// B tile: 128 j-rows x 64 k cols bf16, stride 144B.
// ===========================================================================
#define A_STRIDE 272
#define A_TILE   (64 * A_STRIDE)            // 17408
#define B_STRIDE 144
#define B_TILE   (128 * B_STRIDE)           // 18432
#define OFF_AH   0
#define OFF_AL   A_TILE
#define OFF_BH   (2 * A_TILE)
#define OFF_BL   (2 * A_TILE + B_TILE)
#define BUF_SZ   (2 * A_TILE + 2 * B_TILE)  // 71680
#define GEMM_SMEM (2 * BUF_SZ)              // 143360

__global__ void __launch_bounds__(256) gemm_kernel(int layer) {
    extern __shared__ char smem[];
    int tid  = threadIdx.x;
    int wid  = tid >> 5;
    int lane = tid & 31;
    int row0 = blockIdx.x * 128;          // in [0, B*L)
    int j0   = blockIdx.y * 128;
    int b    = row0 >> 12;
    int l0   = row0 & (LSEQ - 1);

    const __nv_bfloat16* Ah = g_yh + ((size_t)(b * HCH)) * LSEQ + l0;
    const __nv_bfloat16* Al = g_yl + ((size_t)(b * HCH)) * LSEQ + l0;
    const __nv_bfloat16* Bh = g_wh + ((size_t)layer * 512 + j0) * HCH;
    const __nv_bfloat16* Bl = g_wl + ((size_t)layer * 512 + j0) * HCH;

    uint32_t sb = smem_u32(smem);

    // staging maps
    int a_kr  = tid >> 4;        // 0..15 (then +16*i)
    int a_seg = tid & 15;        // 16B segment of 256B row
    int b_jr  = tid >> 3;        // 0..31 (then +32*i)
    int b_seg = tid & 7;

    float acc[2][8][4];
#pragma unroll
    for (int mt = 0; mt < 2; mt++)
#pragma unroll
        for (int nt = 0; nt < 8; nt++)
#pragma unroll
            for (int e = 0; e < 4; e++) acc[mt][nt][e] = 0.0f;

    int wm = wid >> 1;        // 0..3  (32-row group)
    int wn = wid & 1;         // 0..1  (64-j group)

    // stage chunk 0
    {
        uint32_t base = sb;
#pragma unroll
        for (int i = 0; i < 4; i++) {
            int kr = a_kr + i * 16;
            uint32_t d = base + kr * A_STRIDE + a_seg * 16;
            size_t go = (size_t)kr * LSEQ + a_seg * 8;
            cp16(d + OFF_AH, Ah + go);
            cp16(d + OFF_AL, Al + go);
        }
#pragma unroll
        for (int i = 0; i < 4; i++) {
            int jr = b_jr + i * 32;
            uint32_t d = base + jr * B_STRIDE + b_seg * 16;
            size_t go = (size_t)jr * HCH + b_seg * 8;
            cp16(d + OFF_BH, Bh + go);
            cp16(d + OFF_BL, Bl + go);
        }
        CP_COMMIT();
    }

    // A fragment address pieces (trans ldmatrix)
    int f_kr = (lane & 7) + ((lane >> 4) << 3);   // source k row 0..15
    int f_mc = ((lane >> 3) & 1) * 8;             // m col 0 or 8

    int buf = 0;
    for (int ch = 0; ch < 4; ch++) {
        if (ch < 3) {
            uint32_t base = sb + (buf ^ 1) * BUF_SZ;
            int k0 = (ch + 1) * 64;
#pragma unroll
            for (int i = 0; i < 4; i++) {
                int kr = a_kr + i * 16;
                uint32_t d = base + kr * A_STRIDE + a_seg * 16;
                size_t go = (size_t)(k0 + kr) * LSEQ + a_seg * 8;
                cp16(d + OFF_AH, Ah + go);
                cp16(d + OFF_AL, Al + go);
            }
#pragma unroll
            for (int i = 0; i < 4; i++) {
                int jr = b_jr + i * 32;
                uint32_t d = base + jr * B_STRIDE + b_seg * 16;
                size_t go = (size_t)jr * HCH + k0 + b_seg * 8;
                cp16(d + OFF_BH, Bh + go);
                cp16(d + OFF_BL, Bl + go);
            }
            CP_COMMIT();
            CP_WAIT1();
        } else {
            CP_WAIT0();
        }
        __syncthreads();

        uint32_t cbase = sb + buf * BUF_SZ;
#pragma unroll
        for (int pass = 0; pass < 3; pass++) {
            uint32_t aoff = cbase + (pass == 2 ? OFF_AL : OFF_AH);
            uint32_t boff = cbase + (pass == 1 ? OFF_BL : OFF_BH);
#pragma unroll
            for (int ks = 0; ks < 4; ks++) {
                uint32_t afrag[2][4];
#pragma unroll
                for (int mt = 0; mt < 2; mt++) {
                    uint32_t aa = aoff + (ks * 16 + f_kr) * A_STRIDE +
                                  (wm * 32 + mt * 16 + f_mc) * 2;
                    ldsm4t(afrag[mt], aa);
                }
                uint32_t bfrag[4][4];
#pragma unroll
                for (int np = 0; np < 4; np++) {
                    uint32_t ba = boff +
                        (wn * 64 + np * 16 + (lane & 15)) * B_STRIDE +
                        ks * 32 + (lane >> 4) * 16;
                    ldsm4(bfrag[np], ba);
                }
#pragma unroll
                for (int mt = 0; mt < 2; mt++)
#pragma unroll
                    for (int nt = 0; nt < 8; nt++) {
                        const uint32_t* bf = bfrag[nt >> 1];
                        uint32_t b0 = (nt & 1) ? bf[1] : bf[0];
                        uint32_t b1 = (nt & 1) ? bf[3] : bf[2];
                        mma_bf16(acc[mt][nt], afrag[mt], b0, b1);
                    }
            }
        }
        __syncthreads();
        buf ^= 1;
    }

    // store
    float* gout = g_g + (size_t)row0 * 512 + j0;
#pragma unroll
    for (int mt = 0; mt < 2; mt++)
#pragma unroll
        for (int nt = 0; nt < 8; nt++) {
            int r = wm * 32 + mt * 16 + (lane >> 2);
            int c = wn * 64 + nt * 8 + (lane & 3) * 2;
            float2 v0 = make_float2(acc[mt][nt][0], acc[mt][nt][1]);
            float2 v1 = make_float2(acc[mt][nt][2], acc[mt][nt][3]);
            *(float2*)&gout[(size_t)r * 512 + c]       = v0;
            *(float2*)&gout[(size_t)(r + 8) * 512 + c] = v1;
        }
}

// ===========================================================================
// Epilogue: bias + GLU + residual + channel LayerNorm. Per 128-row tile.
// ===========================================================================
#define EPI_SMEM (128 * 257 * 4)

__global__ void __launch_bounds__(512) glu_ln_kernel(
    const float* __restrict__ out_b, const float* __restrict__ ln_w,
    const float* __restrict__ ln_b, int layer) {
    extern __shared__ float usm[];  // [128][257]
    __shared__ float s_ob[512];
    __shared__ float s_lnw[HCH];
    __shared__ float s_lnb[HCH];
    __shared__ float s_mu[128];
    __shared__ float s_rs[128];

    int tid  = threadIdx.x;
    int row0 = blockIdx.x * 128;
    int b    = row0 >> 12;
    int pos0 = row0 & (LSEQ - 1);

    s_ob[tid] = __ldg(&out_b[layer * 512 + tid]);
    if (tid < HCH) {
        s_lnw[tid] = __ldg(&ln_w[layer * HCH + tid]);
        s_lnb[tid] = __ldg(&ln_b[layer * HCH + tid]);
    }
    __syncthreads();

    const float* gg = g_g + (size_t)row0 * 512;
    // phase A: u = (g1+b1) * sigmoid(g2+b2)
#pragma unroll 4
    for (int it = 0; it < 64; it++) {
        int flat = tid + it * 512;
        int p = flat >> 8;
        int h = flat & 255;
        float g1 = gg[(size_t)p * 512 + h] + s_ob[h];
        float g2 = gg[(size_t)p * 512 + 256 + h] + s_ob[256 + h];
        usm[p * 257 + h] = g1 / (1.0f + __expf(-g2));
    }
    __syncthreads();

    // phase B: + residual
    const float* resb = g_h + (size_t)(b * HCH) * LSEQ + pos0;
#pragma unroll 4
    for (int it = 0; it < 64; it++) {
        int flat = tid + it * 512;
        int h = flat >> 7;
        int p = flat & 127;
        usm[p * 257 + h] += resb[(size_t)h * LSEQ + p];
    }
    __syncthreads();

    // phase C: per-pos mean/var over 256 channels
    {
        int w = tid >> 5, lane = tid & 31;
#pragma unroll
        for (int i = 0; i < 8; i++) {
            int pos = w * 8 + i;
            float s = 0.0f, q = 0.0f;
#pragma unroll
            for (int r = 0; r < 8; r++) {
                float v = usm[pos * 257 + lane + r * 32];
                s += v;
                q = fmaf(v, v, q);
            }
#pragma unroll
            for (int off = 16; off > 0; off >>= 1) {
                s += __shfl_xor_sync(0xffffffffu, s, off);
                q += __shfl_xor_sync(0xffffffffu, q, off);
            }
            if (lane == 0) {
                float m = s * (1.0f / 256.0f);
                s_mu[pos] = m;
                s_rs[pos] = rsqrtf(fmaf(-m, m, q * (1.0f / 256.0f)) + 1e-5f);
            }
        }
    }
    __syncthreads();

    // phase D: normalize + write back to g_h
    float* outp = g_h + (size_t)(b * HCH) * LSEQ + pos0;
#pragma unroll 4
    for (int it = 0; it < 64; it++) {
        int flat = tid + it * 512;
        int h = flat >> 7;
        int p = flat & 127;
        float u = usm[p * 257 + h];
        outp[(size_t)h * LSEQ + p] =
            fmaf((u - s_mu[p]) * s_rs[p], s_lnw[h], s_lnb[h]);
    }
}

// ===========================================================================
// Decoder
// ===========================================================================
__global__ void __launch_bounds__(256) decoder_kernel(
    const float* __restrict__ dec_w, const float* __restrict__ dec_b,
    float* __restrict__ out) {
    __shared__ float wsh[DOUT * HCH];
    __shared__ float bsh[DOUT];
    int b    = blockIdx.y;
    int pos0 = blockIdx.x * 256;
    int tid  = threadIdx.x;
    for (int e = tid; e < DOUT * HCH; e += 256) wsh[e] = dec_w[e];
    if (tid < DOUT) bsh[tid] = dec_b[tid];
    __syncthreads();

    float acc[DOUT];
#pragma unroll
    for (int o = 0; o < DOUT; o++) acc[o] = bsh[o];

    const float* hp = g_h + (size_t)b * HCH * LSEQ + pos0 + tid;
    for (int h = 0; h < HCH; h++) {
        float xv = hp[(size_t)h * LSEQ];
#pragma unroll
        for (int o = 0; o < DOUT; o++)
            acc[o] = fmaf(xv, wsh[o * HCH + h], acc[o]);
    }
    float* op = out + ((size_t)(b * LSEQ) + pos0 + tid) * DOUT;
#pragma unroll
    for (int o = 0; o < DOUT; o++) op[o] = acc[o];
}

// ===========================================================================
extern "C" void kernel_launch(void* const* d_in, const int* in_sizes, int n_in,
                              void* d_out, int out_size) {
    const float* x          = (const float*)d_in[0];
    const float* enc_w      = (const float*)d_in[1];
    const float* enc_b      = (const float*)d_in[2];
    const float* log_dt     = (const float*)d_in[3];
    const float* log_A_real = (const float*)d_in[4];
    const float* A_imag     = (const float*)d_in[5];
    const float* C_re       = (const float*)d_in[6];
    const float* C_im       = (const float*)d_in[7];
    const float* Dv         = (const float*)d_in[8];
    const float* out_w      = (const float*)d_in[9];
    const float* out_b      = (const float*)d_in[10];
    const float* ln_w       = (const float*)d_in[11];
    const float* ln_b       = (const float*)d_in[12];
    const float* dec_w      = (const float*)d_in[13];
    const float* dec_b      = (const float*)d_in[14];
    float* out = (float*)d_out;

    size_t enc_smem = (size_t)(64 * HCH + 64 * 68) * sizeof(float);
    cudaFuncSetAttribute(encoder_kernel,
                         cudaFuncAttributeMaxDynamicSharedMemorySize,
                         (int)enc_smem);
    cudaFuncSetAttribute(gemm_kernel,
                         cudaFuncAttributeMaxDynamicSharedMemorySize,
                         GEMM_SMEM);
    cudaFuncSetAttribute(glu_ln_kernel,
                         cudaFuncAttributeMaxDynamicSharedMemorySize,
                         EPI_SMEM);

    params_kernel<<<(NLAY * HCH * NST + 255) / 256, 256>>>(
        log_dt, log_A_real, A_imag, C_re, C_im);
    wsplit_kernel<<<(NLAY * 512 * HCH + 255) / 256, 256>>>(out_w);
    encoder_kernel<<<dim3(LSEQ / 64, NBATCH), 256, enc_smem>>>(x, enc_w, enc_b);
    for (int layer = 0; layer < NLAY; layer++) {
        scan_kernel<<<512, 256>>>(Dv, layer);
        gemm_kernel<<<dim3(NBATCH * LSEQ / 128, 4), 256, GEMM_SMEM>>>(layer);
        glu_ln_kernel<<<NBATCH * LSEQ / 128, 512, EPI_SMEM>>>(
            out_b, ln_w, ln_b, layer);
    }
    decoder_kernel<<<dim3(LSEQ / 256, NBATCH), 256>>>(dec_w, dec_b, out);
}

// round 7
// speedup vs baseline: 1.3699x; 1.1207x over previous
#include <cuda_runtime.h>
#include <cuda_bf16.h>
#include <math.h>
#include <stdint.h>

#define NBATCH 16
#define LSEQ   4096
#define DIN    64
#define HCH    256
#define NST    32
#define NLAY   4
#define DOUT   10

// ===========================================================================
// Base-ISA PTX helpers (compute_103 base — no tcgen05 / 'a'-suffix features)
// ===========================================================================
__device__ __forceinline__ uint32_t smem_u32(const void* p) {
    uint32_t a;
    asm("{ .reg .u64 t; cvta.to.shared.u64 t, %1; cvt.u32.u64 %0, t; }"
        : "=r"(a) : "l"(p));
    return a;
}
__device__ __forceinline__ void cp16(uint32_t dst, const void* src) {
    asm volatile("cp.async.cg.shared.global [%0], [%1], 16;"
                 :: "r"(dst), "l"(src));
}
#define CP_COMMIT() asm volatile("cp.async.commit_group;" ::: "memory")
#define CP_WAIT0()  asm volatile("cp.async.wait_group 0;" ::: "memory")
#define CP_WAIT1()  asm volatile("cp.async.wait_group 1;" ::: "memory")

__device__ __forceinline__ void ldsm4(uint32_t* r, uint32_t addr) {
    asm volatile("ldmatrix.sync.aligned.m8n8.x4.shared.b16 {%0,%1,%2,%3}, [%4];"
                 : "=r"(r[0]), "=r"(r[1]), "=r"(r[2]), "=r"(r[3]) : "r"(addr));
}
__device__ __forceinline__ void ldsm4t(uint32_t* r, uint32_t addr) {
    asm volatile("ldmatrix.sync.aligned.m8n8.x4.trans.shared.b16 {%0,%1,%2,%3}, [%4];"
                 : "=r"(r[0]), "=r"(r[1]), "=r"(r[2]), "=r"(r[3]) : "r"(addr));
}
__device__ __forceinline__ void mma_bf16(float* d, const uint32_t* a,
                                         uint32_t b0, uint32_t b1) {
    asm volatile(
        "mma.sync.aligned.m16n8k16.row.col.f32.bf16.bf16.f32 "
        "{%0,%1,%2,%3}, {%4,%5,%6,%7}, {%8,%9}, {%0,%1,%2,%3};"
        : "+f"(d[0]), "+f"(d[1]), "+f"(d[2]), "+f"(d[3])
        : "r"(a[0]), "r"(a[1]), "r"(a[2]), "r"(a[3]), "r"(b0), "r"(b1));
}

// ===========================================================================
// Packed fp32x2 helpers (encoder)
// ===========================================================================
__device__ __forceinline__ unsigned long long pack2(float x, float y) {
    unsigned long long r;
    asm("mov.b64 %0, {%1, %2};" : "=l"(r) : "f"(x), "f"(y));
    return r;
}
__device__ __forceinline__ void fma2(unsigned long long& d,
                                     unsigned long long a,
                                     unsigned long long b) {
    asm("fma.rn.f32x2 %0, %1, %2, %0;" : "+l"(d) : "l"(a), "l"(b));
}
__device__ __forceinline__ float2 unpack2(unsigned long long v) {
    float2 r;
    asm("mov.b64 {%0, %1}, %2;" : "=f"(r.x), "=f"(r.y) : "l"(v));
    return r;
}

// ===========================================================================
// Device scratch
// ===========================================================================
__device__ float g_h[NBATCH * HCH * LSEQ];                       // (B,H,L)
__device__ __nv_bfloat16 g_yh[(size_t)NBATCH * HCH * LSEQ];      // y hi, [c][l]
__device__ __nv_bfloat16 g_yl[(size_t)NBATCH * HCH * LSEQ];      // y lo, [c][l]
__device__ __nv_bfloat16 g_wh[NLAY * 512 * HCH];                 // out_w hi
__device__ __nv_bfloat16 g_wl[NLAY * 512 * HCH];                 // out_w lo
__device__ float g_par[NLAY][4][HCH * NST];

// ===========================================================================
// SSM parameter precompute
// ===========================================================================
__global__ void params_kernel(const float* __restrict__ log_dt,
                              const float* __restrict__ log_A_real,
                              const float* __restrict__ A_imag,
                              const float* __restrict__ C_re,
                              const float* __restrict__ C_im) {
    int idx = blockIdx.x * blockDim.x + threadIdx.x;
    if (idx >= NLAY * HCH * NST) return;
    int layer = idx / (HCH * NST);
    int hn    = idx - layer * (HCH * NST);
    int h     = hn / NST;

    float dt  = expf(log_dt[layer * HCH + h]);
    float Are = -expf(log_A_real[idx]);
    float Aim = A_imag[idx];
    float dre = Are * dt;
    float dimg = Aim * dt;

    float sy, cy;
    sincosf(dimg, &sy, &cy);
    float em1 = expm1f(dre);
    float ex  = em1 + 1.0f;
    float wre = ex * cy;
    float wim = ex * sy;
    float emr = fmaf(em1, cy, cy - 1.0f);
    float emi = ex * sy;

    float inv = 1.0f / fmaf(Are, Are, Aim * Aim);
    float tre = fmaf(emr, Are, emi * Aim) * inv;
    float tim = fmaf(emi, Are, -emr * Aim) * inv;

    float cre = C_re[idx], cim = C_im[idx];
    float ctre = fmaf(cre, tre, -cim * tim);
    float ctim = fmaf(cre, tim, cim * tre);

    g_par[layer][0][hn] = wre;
    g_par[layer][1][hn] = wim;
    g_par[layer][2][hn] = 2.0f * ctre;
    g_par[layer][3][hn] = -2.0f * ctim;
}

// ===========================================================================
// out_w bf16 hi/lo split (once)
// ===========================================================================
__global__ void wsplit_kernel(const float* __restrict__ out_w) {
    int idx = blockIdx.x * blockDim.x + threadIdx.x;
    if (idx >= NLAY * 512 * HCH) return;
    float w = out_w[idx];
    __nv_bfloat16 hi = __float2bfloat16(w);
    g_wh[idx] = hi;
    g_wl[idx] = __float2bfloat16(w - __bfloat162float(hi));
}

// ===========================================================================
// Encoder
// ===========================================================================
__global__ void __launch_bounds__(256) encoder_kernel(
    const float* __restrict__ x,
    const float* __restrict__ enc_w,
    const float* __restrict__ enc_b) {
    extern __shared__ float sm[];
    float* Wsh = sm;               // [64][256]
    float* Xsh = sm + 64 * HCH;    // [64][68]

    int b    = blockIdx.y;
    int pos0 = blockIdx.x * 64;
    int tid  = threadIdx.x;

    {
        const float4* wrow = (const float4*)(enc_w + (size_t)tid * DIN);
#pragma unroll
        for (int q = 0; q < 16; q++) {
            float4 v = wrow[q];
            Wsh[(q * 4 + 0) * HCH + tid] = v.x;
            Wsh[(q * 4 + 1) * HCH + tid] = v.y;
            Wsh[(q * 4 + 2) * HCH + tid] = v.z;
            Wsh[(q * 4 + 3) * HCH + tid] = v.w;
        }
    }
    {
#pragma unroll
        for (int k = 0; k < 4; k++) {
            int e  = tid + k * 256;
            int l  = e >> 4;
            int i4 = e & 15;
            const float4* xr =
                (const float4*)(x + ((size_t)(b * LSEQ) + pos0 + l) * DIN);
            float4 v = xr[i4];
            Xsh[(i4 * 4 + 0) * 68 + l] = v.x;
            Xsh[(i4 * 4 + 1) * 68 + l] = v.y;
            Xsh[(i4 * 4 + 2) * 68 + l] = v.z;
            Xsh[(i4 * 4 + 3) * 68 + l] = v.w;
        }
    }
    __syncthreads();

    int th = tid >> 3;
    int tl = tid & 7;
    unsigned long long acc2[8][4];
#pragma unroll
    for (int r = 0; r < 8; r++)
#pragma unroll
        for (int c = 0; c < 4; c++) acc2[r][c] = 0ULL;

    for (int i = 0; i < DIN; i++) {
        float4 a0 = *(const float4*)&Wsh[i * HCH + th * 8];
        float4 a1 = *(const float4*)&Wsh[i * HCH + th * 8 + 4];
        ulonglong2 b0 = *(const ulonglong2*)&Xsh[i * 68 + tl * 8];
        ulonglong2 b1 = *(const ulonglong2*)&Xsh[i * 68 + tl * 8 + 4];
        unsigned long long bv[4] = {b0.x, b0.y, b1.x, b1.y};
        float av[8] = {a0.x, a0.y, a0.z, a0.w, a1.x, a1.y, a1.z, a1.w};
#pragma unroll
        for (int r = 0; r < 8; r++) {
            unsigned long long ar = pack2(av[r], av[r]);
#pragma unroll
            for (int c = 0; c < 4; c++) fma2(acc2[r][c], ar, bv[c]);
        }
    }

#pragma unroll
    for (int r = 0; r < 8; r++) {
        int h = th * 8 + r;
        float bias = __ldg(&enc_b[h]);
        float* dst = g_h + ((size_t)(b * HCH + h)) * LSEQ + pos0 + tl * 8;
        float2 p0 = unpack2(acc2[r][0]);
        float2 p1 = unpack2(acc2[r][1]);
        float2 p2 = unpack2(acc2[r][2]);
        float2 p3 = unpack2(acc2[r][3]);
        float4 o0 = make_float4(p0.x + bias, p0.y + bias, p1.x + bias, p1.y + bias);
        float4 o1 = make_float4(p2.x + bias, p2.y + bias, p3.x + bias, p3.y + bias);
        ((float4*)dst)[0] = o0;
        ((float4*)dst)[1] = o1;
    }
}

// ===========================================================================
// SSM scan + D-skip + GELU -> bf16 hi/lo in natural [c][l] layout.
// ===========================================================================
__global__ void __launch_bounds__(256) scan_kernel(const float* __restrict__ Dvec,
                                                   int layer) {
    __shared__ float sh[8][32][33];
    int tid  = threadIdx.x;
    int wid  = tid >> 5;
    int lane = tid & 31;
    int c    = blockIdx.x * 8 + wid;
    int h    = c & (HCH - 1);

    const float* par = &g_par[layer][0][0];
    float wre = par[0 * (HCH * NST) + h * NST + lane];
    float wim = par[1 * (HCH * NST) + h * NST + lane];
    float ca  = par[2 * (HCH * NST) + h * NST + lane];
    float cb  = par[3 * (HCH * NST) + h * NST + lane];
    float Dh  = __ldg(&Dvec[layer * HCH + h]);

    const float* zin = g_h + (size_t)c * LSEQ;
    __nv_bfloat16* yh = g_yh + (size_t)c * LSEQ;
    __nv_bfloat16* yl = g_yl + (size_t)c * LSEQ;
    float (*S)[33] = sh[wid];

    float sre = 0.0f, sim = 0.0f;
    float zv = zin[lane];
    for (int l0 = 0; l0 < LSEQ; l0 += 32) {
        float zn = (l0 + 32 < LSEQ) ? zin[l0 + 32 + lane] : 0.0f;
#pragma unroll
        for (int t = 0; t < 32; t++) {
            float z  = __shfl_sync(0xffffffffu, zv, t);
            float nr = fmaf(wre, sre, z);
            nr       = fmaf(-wim, sim, nr);
            float ni = fmaf(wim, sre, wre * sim);
            sre = nr;
            sim = ni;
            S[lane][t] = fmaf(ca, sre, cb * sim);
        }
        __syncwarp();
        float acc = 0.0f;
#pragma unroll
        for (int n = 0; n < 32; n++) acc += S[n][lane];
        float yv = fmaf(Dh, zv, acc);
        float u  = 0.7978845608028654f * fmaf(0.044715f, yv * yv * yv, yv);
        float gv = yv / (1.0f + __expf(-2.0f * u));
        __nv_bfloat16 bh = __float2bfloat16(gv);
        __nv_bfloat16 bl = __float2bfloat16(gv - __bfloat162float(bh));
        yh[l0 + lane] = bh;
        yl[l0 + lane] = bl;
        __syncwarp();
        zv = zn;
    }
}

// ===========================================================================
// FUSED: HMMA GEMM (bf16 3-pass, fp32 acc) + bias + GLU + residual + channel
// LayerNorm, all in one kernel. CTA = 64 rows x ALL 512 j, 8 warps:
// warp = (m-tile mt = wid>>1 [16 rows], j-half jh = wid&1 [256 j]).
// k-chunks of 32, cp.async double-buffered.
// A tile: 32 k-rows x 64 pos cols bf16 (128B data, 144B stride, trans ldsm).
// B tile: 512 j-rows x 32 k cols bf16 (64B data, 80B stride).
// Epilogue (smem aliased over tiles): Gs2[64][260] f32, Rsm[64][260] f32.
// ===========================================================================
#define FA_STRIDE 144
#define FA_TILE   (32 * FA_STRIDE)                 // 4608
#define FB_STRIDE 80
#define FB_TILE   (512 * FB_STRIDE)                // 40960
#define F_AH      0
#define F_AL      FA_TILE
#define F_BH      (2 * FA_TILE)
#define F_BL      (2 * FA_TILE + FB_TILE)
#define F_BUF     (2 * FA_TILE + 2 * FB_TILE)      // 91136
#define FUSED_SMEM (2 * F_BUF)                     // 182272
#define EPI_G2    0                                // f32 [64][260]
#define EPI_RES   (64 * 260 * 4)                   // f32 [64][260]

__global__ void __launch_bounds__(256, 1) fused_glu_ln_kernel(
    const float* __restrict__ out_b, const float* __restrict__ ln_w,
    const float* __restrict__ ln_b, int layer) {
    extern __shared__ char smem[];
    __shared__ float s_ob[512];
    __shared__ float s_lnw[HCH];
    __shared__ float s_lnb[HCH];
    __shared__ float s_mu[64];
    __shared__ float s_rs[64];

    int tid  = threadIdx.x;
    int wid  = tid >> 5;
    int lane = tid & 31;
    int row0 = blockIdx.x * 64;           // position rows, in [0, B*L)
    int b    = row0 >> 12;
    int pos0 = row0 & (LSEQ - 1);

    // blockDim is 256: load BOTH halves of out_b (512 entries).
    s_ob[tid]       = __ldg(&out_b[layer * 512 + tid]);
    s_ob[tid + 256] = __ldg(&out_b[layer * 512 + tid + 256]);
    if (tid < HCH) {
        s_lnw[tid] = __ldg(&ln_w[layer * HCH + tid]);
        s_lnb[tid] = __ldg(&ln_b[layer * HCH + tid]);
    }

    const __nv_bfloat16* Ah = g_yh + ((size_t)(b * HCH)) * LSEQ + pos0;
    const __nv_bfloat16* Al = g_yl + ((size_t)(b * HCH)) * LSEQ + pos0;
    const __nv_bfloat16* Bh = g_wh + (size_t)layer * 512 * HCH;
    const __nv_bfloat16* Bl = g_wl + (size_t)layer * 512 * HCH;

    uint32_t sb = smem_u32(smem);

    // staging maps
    int a_kr  = tid >> 3;        // 0..31 k-row
    int a_seg = tid & 7;         // 16B segment of 128B row
    int b_jr0 = tid >> 2;        // 0..63 (then +64*i)
    int b_seg = tid & 3;         // 16B segment of 64B row

    float acc[32][4];
#pragma unroll
    for (int nt = 0; nt < 32; nt++)
#pragma unroll
        for (int e = 0; e < 4; e++) acc[nt][e] = 0.0f;

    int mt = wid >> 1;           // 0..3 (16-row group)
    int jh = wid & 1;            // 0..1 (256-j half)

    // stage chunk 0
    {
        uint32_t base = sb;
        {
            uint32_t d = base + a_kr * FA_STRIDE + a_seg * 16;
            size_t go = (size_t)a_kr * LSEQ + a_seg * 8;
            cp16(d + F_AH, Ah + go);
            cp16(d + F_AL, Al + go);
        }
#pragma unroll
        for (int i = 0; i < 8; i++) {
            int jr = b_jr0 + i * 64;
            uint32_t d = base + jr * FB_STRIDE + b_seg * 16;
            size_t go = (size_t)jr * HCH + b_seg * 8;
            cp16(d + F_BH, Bh + go);
            cp16(d + F_BL, Bl + go);
        }
        CP_COMMIT();
    }

    // A fragment address pieces (trans ldmatrix)
    int f_kr = (lane & 7) + ((lane >> 4) << 3);   // source k row 0..15
    int f_mc = ((lane >> 3) & 1) * 8;             // m col 0 or 8

    int buf = 0;
    for (int ch = 0; ch < 8; ch++) {
        if (ch < 7) {
            uint32_t base = sb + (buf ^ 1) * F_BUF;
            int k0 = (ch + 1) * 32;
            {
                uint32_t d = base + a_kr * FA_STRIDE + a_seg * 16;
                size_t go = (size_t)(k0 + a_kr) * LSEQ + a_seg * 8;
                cp16(d + F_AH, Ah + go);
                cp16(d + F_AL, Al + go);
            }
#pragma unroll
            for (int i = 0; i < 8; i++) {
                int jr = b_jr0 + i * 64;
                uint32_t d = base + jr * FB_STRIDE + b_seg * 16;
                size_t go = (size_t)jr * HCH + k0 + b_seg * 8;
                cp16(d + F_BH, Bh + go);
                cp16(d + F_BL, Bl + go);
            }
            CP_COMMIT();
            CP_WAIT1();
        } else {
            CP_WAIT0();
        }
        __syncthreads();

        uint32_t cbase = sb + buf * F_BUF;
#pragma unroll
        for (int pass = 0; pass < 3; pass++) {
            uint32_t aoff = cbase + (pass == 2 ? F_AL : F_AH);
            uint32_t boff = cbase + (pass == 1 ? F_BL : F_BH);
#pragma unroll
            for (int ks = 0; ks < 2; ks++) {
                uint32_t afrag[4];
                ldsm4t(afrag, aoff + (ks * 16 + f_kr) * FA_STRIDE +
                              (mt * 16 + f_mc) * 2);
#pragma unroll
                for (int grp = 0; grp < 4; grp++) {
                    uint32_t bfrag[4][4];
#pragma unroll
                    for (int gg = 0; gg < 4; gg++) {
                        int ng = grp * 4 + gg;
                        uint32_t ba = boff +
                            (jh * 256 + ng * 16 + (lane & 15)) * FB_STRIDE +
                            ks * 32 + (lane >> 4) * 16;
                        ldsm4(bfrag[gg], ba);
                    }
#pragma unroll
                    for (int gg = 0; gg < 4; gg++) {
                        int ng = grp * 4 + gg;
                        mma_bf16(acc[ng * 2],     afrag, bfrag[gg][0], bfrag[gg][2]);
                        mma_bf16(acc[ng * 2 + 1], afrag, bfrag[gg][1], bfrag[gg][3]);
                    }
                }
            }
        }
        __syncthreads();
        buf ^= 1;
    }

    // ---------------- fused epilogue (aliases tile smem) ----------------
    float* Gs2 = (float*)(smem + EPI_G2);    // [64][260]
    float* Rsm = (float*)(smem + EPI_RES);   // [64][260]

    // stage residual Rsm[pos][h] (all threads, coalesced over pos)
    {
        const float* resb = g_h + (size_t)(b * HCH) * LSEQ + pos0;
#pragma unroll
        for (int i = 0; i < 16; i++) {
            int flat = tid + i * 256;        // 0..4095
            int h    = flat >> 4;
            int sg   = flat & 15;
            float4 v = *(const float4*)(resb + (size_t)h * LSEQ + sg * 4);
            Rsm[(sg * 4 + 0) * 260 + h] = v.x;
            Rsm[(sg * 4 + 1) * 260 + h] = v.y;
            Rsm[(sg * 4 + 2) * 260 + h] = v.z;
            Rsm[(sg * 4 + 3) * 260 + h] = v.w;
        }
    }
    // jh1 warps: write g2 + bias into Gs2
    if (jh == 1) {
#pragma unroll
        for (int nt = 0; nt < 32; nt++) {
            int h = nt * 8 + (lane & 3) * 2;
            int r = mt * 16 + (lane >> 2);
            float bb0 = s_ob[256 + h];
            float bb1 = s_ob[256 + h + 1];
            Gs2[r * 260 + h]           = acc[nt][0] + bb0;
            Gs2[r * 260 + h + 1]       = acc[nt][1] + bb1;
            Gs2[(r + 8) * 260 + h]     = acc[nt][2] + bb0;
            Gs2[(r + 8) * 260 + h + 1] = acc[nt][3] + bb1;
        }
    }
    __syncthreads();

    // jh0 warps: u = (g1+b1)*sigmoid(g2) + res, stored in place in Gs2
    if (jh == 0) {
#pragma unroll
        for (int nt = 0; nt < 32; nt++) {
            int h = nt * 8 + (lane & 3) * 2;
            int r = mt * 16 + (lane >> 2);
            float bb0 = s_ob[h];
            float bb1 = s_ob[h + 1];
#pragma unroll
            for (int e = 0; e < 4; e++) {
                int rr = r + ((e >> 1) << 3);
                int hh = h + (e & 1);
                float g1 = acc[nt][e] + ((e & 1) ? bb1 : bb0);
                float g2 = Gs2[rr * 260 + hh];
                float u  = fmaf(g1, 1.0f / (1.0f + __expf(-g2)),
                                Rsm[rr * 260 + hh]);
                Gs2[rr * 260 + hh] = u;
            }
        }
    }
    __syncthreads();

    // per-row stats (4 threads per row)
    {
        int r = tid >> 2;
        int q = tid & 3;
        float s = 0.0f, sq = 0.0f;
#pragma unroll
        for (int i = 0; i < 64; i++) {
            float v = Gs2[r * 260 + q * 64 + i];
            s += v;
            sq = fmaf(v, v, sq);
        }
        s  += __shfl_xor_sync(0xffffffffu, s, 1);
        sq += __shfl_xor_sync(0xffffffffu, sq, 1);
        s  += __shfl_xor_sync(0xffffffffu, s, 2);
        sq += __shfl_xor_sync(0xffffffffu, sq, 2);
        if (q == 0) {
            float m = s * (1.0f / 256.0f);
            s_mu[r] = m;
            s_rs[r] = rsqrtf(fmaf(-m, m, sq * (1.0f / 256.0f)) + 1e-5f);
        }
    }
    __syncthreads();

    // normalize + transposed coalesced write: thread h' writes 64 positions
    {
        int h = tid;
        float w  = s_lnw[h];
        float bb = s_lnb[h];
        float* outp = g_h + ((size_t)(b * HCH + h)) * LSEQ + pos0;
#pragma unroll
        for (int p4 = 0; p4 < 16; p4++) {
            float4 o;
            float u0 = Gs2[(p4 * 4 + 0) * 260 + h];
            float u1 = Gs2[(p4 * 4 + 1) * 260 + h];
            float u2 = Gs2[(p4 * 4 + 2) * 260 + h];
            float u3 = Gs2[(p4 * 4 + 3) * 260 + h];
            o.x = fmaf((u0 - s_mu[p4 * 4 + 0]) * s_rs[p4 * 4 + 0], w, bb);
            o.y = fmaf((u1 - s_mu[p4 * 4 + 1]) * s_rs[p4 * 4 + 1], w, bb);
            o.z = fmaf((u2 - s_mu[p4 * 4 + 2]) * s_rs[p4 * 4 + 2], w, bb);
            o.w = fmaf((u3 - s_mu[p4 * 4 + 3]) * s_rs[p4 * 4 + 3], w, bb);
            *(float4*)(outp + p4 * 4) = o;
        }
    }
}

// ===========================================================================
// Decoder
// ===========================================================================
__global__ void __launch_bounds__(256) decoder_kernel(
    const float* __restrict__ dec_w, const float* __restrict__ dec_b,
    float* __restrict__ out) {
    __shared__ float wsh[DOUT * HCH];
    __shared__ float bsh[DOUT];
    int b    = blockIdx.y;
    int pos0 = blockIdx.x * 256;
    int tid  = threadIdx.x;
    for (int e = tid; e < DOUT * HCH; e += 256) wsh[e] = dec_w[e];
    if (tid < DOUT) bsh[tid] = dec_b[tid];
    __syncthreads();

    float acc[DOUT];
#pragma unroll
    for (int o = 0; o < DOUT; o++) acc[o] = bsh[o];

    const float* hp = g_h + (size_t)b * HCH * LSEQ + pos0 + tid;
    for (int h = 0; h < HCH; h++) {
        float xv = hp[(size_t)h * LSEQ];
#pragma unroll
        for (int o = 0; o < DOUT; o++)
            acc[o] = fmaf(xv, wsh[o * HCH + h], acc[o]);
    }
    float* op = out + ((size_t)(b * LSEQ) + pos0 + tid) * DOUT;
#pragma unroll
    for (int o = 0; o < DOUT; o++) op[o] = acc[o];
}

// ===========================================================================
extern "C" void kernel_launch(void* const* d_in, const int* in_sizes, int n_in,
                              void* d_out, int out_size) {
    const float* x          = (const float*)d_in[0];
    const float* enc_w      = (const float*)d_in[1];
    const float* enc_b      = (const float*)d_in[2];
    const float* log_dt     = (const float*)d_in[3];
    const float* log_A_real = (const float*)d_in[4];
    const float* A_imag     = (const float*)d_in[5];
    const float* C_re       = (const float*)d_in[6];
    const float* C_im       = (const float*)d_in[7];
    const float* Dv         = (const float*)d_in[8];
    const float* out_w      = (const float*)d_in[9];
    const float* out_b      = (const float*)d_in[10];
    const float* ln_w       = (const float*)d_in[11];
    const float* ln_b       = (const float*)d_in[12];
    const float* dec_w      = (const float*)d_in[13];
    const float* dec_b      = (const float*)d_in[14];
    float* out = (float*)d_out;

    size_t enc_smem = (size_t)(64 * HCH + 64 * 68) * sizeof(float);
    cudaFuncSetAttribute(encoder_kernel,
                         cudaFuncAttributeMaxDynamicSharedMemorySize,
                         (int)enc_smem);
    cudaFuncSetAttribute(fused_glu_ln_kernel,
                         cudaFuncAttributeMaxDynamicSharedMemorySize,
                         FUSED_SMEM);

    params_kernel<<<(NLAY * HCH * NST + 255) / 256, 256>>>(
        log_dt, log_A_real, A_imag, C_re, C_im);
    wsplit_kernel<<<(NLAY * 512 * HCH + 255) / 256, 256>>>(out_w);
    encoder_kernel<<<dim3(LSEQ / 64, NBATCH), 256, enc_smem>>>(x, enc_w, enc_b);
    for (int layer = 0; layer < NLAY; layer++) {
        scan_kernel<<<512, 256>>>(Dv, layer);
        fused_glu_ln_kernel<<<NBATCH * LSEQ / 64, 256, FUSED_SMEM>>>(
            out_b, ln_w, ln_b, layer);
    }
    decoder_kernel<<<dim3(LSEQ / 256, NBATCH), 256>>>(dec_w, dec_b, out);
}